// round 1
// baseline (speedup 1.0000x reference)
#include <cuda_runtime.h>
#include <cuda_bf16.h>
#include <math.h>

// Problem constants
#define B_ 2
#define L_ 1024
#define H_ 256
#define NH_ 8
#define DH_ 32
#define FF_ 1024
#define NL_ 2
#define REL_ 100
#define M_ (B_ * L_)            // 2048 rows
#define INV_SCALE 0.17677669529663687f   // 1/sqrt(32)
#define EPS_ 1e-5f

// ---------------- scratch (device globals; no runtime alloc) ----------------
__device__ float g_x[M_ * H_];
__device__ float g_q[M_ * H_];
__device__ float g_k[M_ * H_];
__device__ float g_v[M_ * H_];
__device__ float g_qrel[M_ * NH_ * REL_];
__device__ float g_att[B_ * NH_ * L_ * L_];   // 64 MB attention probs
__device__ float g_ao[M_ * H_];
__device__ float g_tmp[M_ * H_];
__device__ float g_ffh[M_ * FF_];
__device__ int   g_mask_mode;                 // 0=int32, 1=uint8, 2=float32

// ---------------- mask dtype detection (deterministic) ----------------
__global__ void detect_mask_kernel(const unsigned char* __restrict__ m) {
    if (threadIdx.x == 0 && blockIdx.x == 0) {
        bool nz12 = false, nz3 = false;
        for (int i = 0; i < 16384; i++) {
            unsigned char v = m[i];
            if (v) {
                int o = i & 3;
                if (o == 1 || o == 2) nz12 = true;
                else if (o == 3) nz3 = true;
            }
        }
        g_mask_mode = nz12 ? 1 : (nz3 ? 2 : 0);
    }
}

__device__ __forceinline__ float mask_neg(const void* maskp, int mm, int idx) {
    if (mm == 0) return ((const int*)maskp)[idx] ? -1e20f : 0.0f;
    if (mm == 1) return ((const unsigned char*)maskp)[idx] ? -1e20f : 0.0f;
    return (((const float*)maskp)[idx] != 0.0f) ? -1e20f : 0.0f;
}

// ---------------- simple copy ----------------
__global__ void copy_kernel(const float* __restrict__ src, float* __restrict__ dst, int n) {
    int i = blockIdx.x * blockDim.x + threadIdx.x;
    if (i < n) dst[i] = src[i];
}

// ---------------- generic SGEMM: C[M,N] = A[M,K] @ B[K,N], row-major ----------------
// 64x64 tile, BK=16, 256 threads, 4x4 microtile. Optional fused bias+ReLU.
__global__ __launch_bounds__(256) void sgemm_k(
    const float* __restrict__ A, const float* __restrict__ Bm,
    float* __restrict__ C, int M, int N, int K,
    const float* __restrict__ bias, int dorelu)
{
    __shared__ float As[64][17];
    __shared__ float Bs[16][64];
    int t = threadIdx.x;
    int tx = t & 15, ty = t >> 4;
    int m0 = blockIdx.y * 64, n0 = blockIdx.x * 64;
    int arow = t >> 2, acol = (t & 3) * 4;
    int brow = t >> 4, bcol = (t & 15) * 4;
    float acc[4][4] = {};
    for (int kk = 0; kk < K; kk += 16) {
        float4 av = *(const float4*)&A[(m0 + arow) * K + kk + acol];
        As[arow][acol + 0] = av.x;
        As[arow][acol + 1] = av.y;
        As[arow][acol + 2] = av.z;
        As[arow][acol + 3] = av.w;
        float4 bv = *(const float4*)&Bm[(kk + brow) * N + n0 + bcol];
        *(float4*)&Bs[brow][bcol] = bv;
        __syncthreads();
#pragma unroll
        for (int k2 = 0; k2 < 16; k2++) {
            float a0 = As[ty * 4 + 0][k2];
            float a1 = As[ty * 4 + 1][k2];
            float a2 = As[ty * 4 + 2][k2];
            float a3 = As[ty * 4 + 3][k2];
            float4 b4 = *(float4*)&Bs[k2][tx * 4];
            acc[0][0] += a0 * b4.x; acc[0][1] += a0 * b4.y; acc[0][2] += a0 * b4.z; acc[0][3] += a0 * b4.w;
            acc[1][0] += a1 * b4.x; acc[1][1] += a1 * b4.y; acc[1][2] += a1 * b4.z; acc[1][3] += a1 * b4.w;
            acc[2][0] += a2 * b4.x; acc[2][1] += a2 * b4.y; acc[2][2] += a2 * b4.z; acc[2][3] += a2 * b4.w;
            acc[3][0] += a3 * b4.x; acc[3][1] += a3 * b4.y; acc[3][2] += a3 * b4.z; acc[3][3] += a3 * b4.w;
        }
        __syncthreads();
    }
    int c0 = n0 + tx * 4;
#pragma unroll
    for (int i = 0; i < 4; i++) {
        int r = m0 + ty * 4 + i;
        float4 o;
        o.x = acc[i][0]; o.y = acc[i][1]; o.z = acc[i][2]; o.w = acc[i][3];
        if (dorelu) {
            o.x = fmaxf(o.x + bias[c0 + 0], 0.0f);
            o.y = fmaxf(o.y + bias[c0 + 1], 0.0f);
            o.z = fmaxf(o.z + bias[c0 + 2], 0.0f);
            o.w = fmaxf(o.w + bias[c0 + 3], 0.0f);
        }
        *(float4*)&C[r * N + c0] = o;
    }
}

// ---------------- qrel: qrel[m, r] = sum_d q[m*32+d] * Ek[r*32+d] (m = (b*L+i)*8+h) ----------------
__global__ __launch_bounds__(256) void qrel_kernel(
    const float* __restrict__ q, const float* __restrict__ Ek, float* __restrict__ qrel)
{
    __shared__ float Eks[REL_ * 33];
    __shared__ float qsm[64 * 32];
    int t = threadIdx.x;
    int r0 = blockIdx.x * 64;   // row block of (M_*NH_) rows
    for (int idx = t; idx < REL_ * 32; idx += 256) {
        int r = idx >> 5, d = idx & 31;
        Eks[r * 33 + d] = Ek[idx];
    }
    for (int idx = t; idx < 64 * 32; idx += 256) qsm[idx] = q[r0 * 32 + idx];
    __syncthreads();
    for (int o = t; o < 64 * REL_; o += 256) {
        int i = o / REL_, r = o % REL_;
        float s = 0.0f;
#pragma unroll 8
        for (int d = 0; d < 32; d++) s += qsm[i * 32 + d] * Eks[r * 33 + d];
        qrel[(r0 + i) * REL_ + r] = s;
    }
}

// ---------------- scores + softmax -> probs ----------------
// grid (L/16, NH, B), 256 threads, dynamic smem.
#define SC_SMEM ((16 * 1024 + 128 * 33 + 16 * 32 + 16 * REL_) * 4)
__global__ __launch_bounds__(256) void scores_kernel(
    const float* __restrict__ q, const float* __restrict__ k,
    const float* __restrict__ qrel, const int* __restrict__ rel,
    const void* __restrict__ maskp, float* __restrict__ a)
{
    extern __shared__ float sm[];
    float* sc = sm;                       // 16*1024
    float* kt = sc + 16 * 1024;           // 128*33
    float* qs = kt + 128 * 33;            // 16*32
    float* qr = qs + 16 * 32;             // 16*100
    int t = threadIdx.x;
    int i0 = blockIdx.x * 16, h = blockIdx.y, b = blockIdx.z;

    for (int idx = t; idx < 16 * 32; idx += 256) {
        int i = idx >> 5, d = idx & 31;
        qs[idx] = q[(b * L_ + i0 + i) * H_ + h * 32 + d];
    }
    for (int idx = t; idx < 16 * REL_; idx += 256) {
        int i = idx / REL_, r = idx % REL_;
        qr[idx] = qrel[((b * L_ + i0 + i) * NH_ + h) * REL_ + r];
    }
    int mm = g_mask_mode;
    int w = t >> 5, l = t & 31;
    int ia = 2 * w, ib = ia + 1;

    for (int jt = 0; jt < 8; jt++) {
        int j0 = jt * 128;
        __syncthreads();
        for (int idx = t; idx < 128 * 32; idx += 256) {
            int j = idx >> 5, d = idx & 31;
            kt[j * 33 + d] = k[(b * L_ + j0 + j) * H_ + h * 32 + d];
        }
        __syncthreads();
        float acc[2][4] = {};
#pragma unroll 4
        for (int d = 0; d < 32; d++) {
            float qa = qs[ia * 32 + d];
            float qb = qs[ib * 32 + d];
#pragma unroll
            for (int c = 0; c < 4; c++) {
                float kv = kt[(l + 32 * c) * 33 + d];
                acc[0][c] += qa * kv;
                acc[1][c] += qb * kv;
            }
        }
#pragma unroll
        for (int c = 0; c < 4; c++) {
            int j = j0 + l + 32 * c;
            int ridxa = (b * L_ + i0 + ia) * L_ + j;
            int ridxb = (b * L_ + i0 + ib) * L_ + j;
            int ra = rel[ridxa];
            int rb = rel[ridxb];
            float na = mask_neg(maskp, mm, ridxa);
            float nb = mask_neg(maskp, mm, ridxb);
            sc[ia * 1024 + j] = (acc[0][c] + qr[ia * REL_ + ra]) * INV_SCALE + na;
            sc[ib * 1024 + j] = (acc[1][c] + qr[ib * REL_ + rb]) * INV_SCALE + nb;
        }
    }
    __syncthreads();

    // softmax: warp w handles rows 2w, 2w+1
    for (int rr = 0; rr < 2; rr++) {
        int i = 2 * w + rr;
        float mx = -3.4e38f;
        for (int j = l; j < 1024; j += 32) mx = fmaxf(mx, sc[i * 1024 + j]);
#pragma unroll
        for (int off = 16; off; off >>= 1) mx = fmaxf(mx, __shfl_xor_sync(0xffffffffu, mx, off));
        float s = 0.0f;
        for (int j = l; j < 1024; j += 32) {
            float e = __expf(sc[i * 1024 + j] - mx);
            sc[i * 1024 + j] = e;
            s += e;
        }
#pragma unroll
        for (int off = 16; off; off >>= 1) s += __shfl_xor_sync(0xffffffffu, s, off);
        float inv = 1.0f / s;
        float* arow = &a[((b * NH_ + h) * L_ + i0 + i) * L_];
        for (int j = l; j < 1024; j += 32) arow[j] = sc[i * 1024 + j] * inv;
    }
}

// ---------------- AV + relation-value: out[b,i,h,:] = A@V + (arel bins)@Ev ----------------
__global__ __launch_bounds__(256) void av_kernel(
    const float* __restrict__ a, const float* __restrict__ v,
    const int* __restrict__ rel, const float* __restrict__ Ev,
    float* __restrict__ out)
{
    __shared__ float vt[128 * 32];
    __shared__ float at[16 * 128];
    __shared__ float arl[16 * REL_];
    __shared__ float Evs[REL_ * 32];
    int t = threadIdx.x;
    int i0 = blockIdx.x * 16, h = blockIdx.y, b = blockIdx.z;
    for (int idx = t; idx < 16 * REL_; idx += 256) arl[idx] = 0.0f;
    for (int idx = t; idx < REL_ * 32; idx += 256) Evs[idx] = Ev[idx];
    int i = t >> 4, d0 = (t & 15) * 2;
    float acc0 = 0.0f, acc1 = 0.0f;
    for (int jt = 0; jt < 8; jt++) {
        int j0 = jt * 128;
        __syncthreads();
        for (int idx = t; idx < 16 * 128; idx += 256) {
            int ii = idx >> 7, j = idx & 127;
            at[idx] = a[((b * NH_ + h) * L_ + i0 + ii) * L_ + j0 + j];
        }
        for (int idx = t; idx < 128 * 32; idx += 256) {
            int j = idx >> 5, d = idx & 31;
            vt[idx] = v[(b * L_ + j0 + j) * H_ + h * 32 + d];
        }
        __syncthreads();
#pragma unroll 8
        for (int j = 0; j < 128; j++) {
            float p = at[i * 128 + j];
            acc0 += p * vt[j * 32 + d0];
            acc1 += p * vt[j * 32 + d0 + 1];
        }
        for (int idx = t; idx < 16 * 128; idx += 256) {
            int ii = idx >> 7, j = idx & 127;
            float p = at[idx];
            if (p != 0.0f) {
                int r = rel[(b * L_ + i0 + ii) * L_ + j0 + j];
                atomicAdd(&arl[ii * REL_ + r], p);
            }
        }
    }
    __syncthreads();
#pragma unroll 4
    for (int r = 0; r < REL_; r++) {
        float wv = arl[i * REL_ + r];
        acc0 += wv * Evs[r * 32 + d0];
        acc1 += wv * Evs[r * 32 + d0 + 1];
    }
    float2 o2;
    o2.x = acc0; o2.y = acc1;
    *(float2*)&out[(b * L_ + i0 + i) * H_ + h * 32 + d0] = o2;
}

// ---------------- bias + residual + LayerNorm (row per CTA, H=256) ----------------
__global__ __launch_bounds__(256) void ln_kernel(
    const float* __restrict__ tin, const float* __restrict__ bias,
    const float* __restrict__ resid, const float* __restrict__ gam,
    const float* __restrict__ bet, float* __restrict__ out)
{
    int row = blockIdx.x, c = threadIdx.x;
    float vv = tin[row * H_ + c] + bias[c] + resid[row * H_ + c];
    __shared__ float red[16];
    float s1 = vv, s2 = vv * vv;
#pragma unroll
    for (int off = 16; off; off >>= 1) {
        s1 += __shfl_xor_sync(0xffffffffu, s1, off);
        s2 += __shfl_xor_sync(0xffffffffu, s2, off);
    }
    int w = c >> 5, l = c & 31;
    if (l == 0) { red[w] = s1; red[8 + w] = s2; }
    __syncthreads();
    float t1 = 0.0f, t2 = 0.0f;
#pragma unroll
    for (int ww = 0; ww < 8; ww++) { t1 += red[ww]; t2 += red[8 + ww]; }
    float mean = t1 * (1.0f / 256.0f);
    float var = t2 * (1.0f / 256.0f) - mean * mean;
    out[row * H_ + c] = (vv - mean) * rsqrtf(var + EPS_) * gam[c] + bet[c];
}

// ---------------- launch ----------------
extern "C" void kernel_launch(void* const* d_in, const int* in_sizes, int n_in,
                              void* d_out, int out_size)
{
    (void)in_sizes; (void)n_in; (void)out_size;
    const float* inputs = (const float*)d_in[0];
    const float* Wq = (const float*)d_in[1];
    const float* Wk = (const float*)d_in[2];
    const float* Wv = (const float*)d_in[3];
    const float* Wo = (const float*)d_in[4];
    const float* bo = (const float*)d_in[5];
    const float* W1 = (const float*)d_in[6];
    const float* b1 = (const float*)d_in[7];
    const float* W2 = (const float*)d_in[8];
    const float* b2 = (const float*)d_in[9];
    const float* ln1g = (const float*)d_in[10];
    const float* ln1b = (const float*)d_in[11];
    const float* ln2g = (const float*)d_in[12];
    const float* ln2b = (const float*)d_in[13];
    const float* Ek = (const float*)d_in[14];
    const float* Ev = (const float*)d_in[15];
    const int*   rel = (const int*)d_in[16];
    const void*  mask = d_in[17];

    float *px, *pq, *pk, *pv, *pqr, *pa, *pao, *ptmp, *pffh;
    cudaGetSymbolAddress((void**)&px,  g_x);
    cudaGetSymbolAddress((void**)&pq,  g_q);
    cudaGetSymbolAddress((void**)&pk,  g_k);
    cudaGetSymbolAddress((void**)&pv,  g_v);
    cudaGetSymbolAddress((void**)&pqr, g_qrel);
    cudaGetSymbolAddress((void**)&pa,  g_att);
    cudaGetSymbolAddress((void**)&pao, g_ao);
    cudaGetSymbolAddress((void**)&ptmp, g_tmp);
    cudaGetSymbolAddress((void**)&pffh, g_ffh);

    cudaFuncSetAttribute(scores_kernel, cudaFuncAttributeMaxDynamicSharedMemorySize, SC_SMEM);

    detect_mask_kernel<<<1, 1>>>((const unsigned char*)mask);
    copy_kernel<<<(M_ * H_ + 255) / 256, 256>>>(inputs, px, M_ * H_);

    for (int l = 0; l < NL_; l++) {
        const float* wq = Wq + l * H_ * H_;
        const float* wk = Wk + l * H_ * H_;
        const float* wv = Wv + l * H_ * H_;
        const float* wo = Wo + l * H_ * H_;
        const float* w1 = W1 + l * H_ * FF_;
        const float* w2 = W2 + l * FF_ * H_;

        sgemm_k<<<dim3(H_ / 64, M_ / 64), 256>>>(px, wq, pq, M_, H_, H_, nullptr, 0);
        sgemm_k<<<dim3(H_ / 64, M_ / 64), 256>>>(px, wk, pk, M_, H_, H_, nullptr, 0);
        sgemm_k<<<dim3(H_ / 64, M_ / 64), 256>>>(px, wv, pv, M_, H_, H_, nullptr, 0);

        qrel_kernel<<<(M_ * NH_) / 64, 256>>>(pq, Ek, pqr);

        scores_kernel<<<dim3(L_ / 16, NH_, B_), 256, SC_SMEM>>>(pq, pk, pqr, rel, mask, pa);
        av_kernel<<<dim3(L_ / 16, NH_, B_), 256>>>(pa, pv, rel, Ev, pao);

        sgemm_k<<<dim3(H_ / 64, M_ / 64), 256>>>(pao, wo, ptmp, M_, H_, H_, nullptr, 0);
        ln_kernel<<<M_, 256>>>(ptmp, bo + l * H_, px, ln1g + l * H_, ln1b + l * H_, px);

        sgemm_k<<<dim3(FF_ / 64, M_ / 64), 256>>>(px, w1, pffh, M_, FF_, H_, b1 + l * FF_, 1);
        sgemm_k<<<dim3(H_ / 64, M_ / 64), 256>>>(pffh, w2, ptmp, M_, H_, FF_, nullptr, 0);

        float* dst = (l == NL_ - 1) ? (float*)d_out : px;
        ln_kernel<<<M_, 256>>>(ptmp, b2 + l * H_, px, ln2g + l * H_, ln2b + l * H_, dst);
    }
}

// round 3
// speedup vs baseline: 1.3427x; 1.3427x over previous
#include <cuda_runtime.h>
#include <cuda_bf16.h>
#include <math.h>

// Problem constants
#define B_ 2
#define L_ 1024
#define H_ 256
#define NH_ 8
#define DH_ 32
#define FF_ 1024
#define NL_ 2
#define REL_ 100
#define M_ (B_ * L_)            // 2048 rows
#define INV_SCALE 0.17677669529663687f   // 1/sqrt(32)
#define EPS_ 1e-5f

// ---------------- scratch (device globals; no runtime alloc) ----------------
__device__ float g_x[M_ * H_];
__device__ float g_q[M_ * H_];
__device__ float g_k[M_ * H_];
__device__ float g_v[M_ * H_];
__device__ float g_qrel[M_ * NH_ * REL_];
__device__ float g_ao[M_ * H_];
__device__ float g_tmp[M_ * H_];
__device__ float g_ffh[M_ * FF_];
__device__ int   g_mask_mode;                 // 0=int32, 1=uint8, 2=float32

// ---------------- mask dtype detection (deterministic) ----------------
__global__ void detect_mask_kernel(const unsigned char* __restrict__ m) {
    if (threadIdx.x == 0 && blockIdx.x == 0) {
        bool nz12 = false, nz3 = false;
        for (int i = 0; i < 16384; i++) {
            unsigned char v = m[i];
            if (v) {
                int o = i & 3;
                if (o == 1 || o == 2) nz12 = true;
                else if (o == 3) nz3 = true;
            }
        }
        g_mask_mode = nz12 ? 1 : (nz3 ? 2 : 0);
    }
}

__device__ __forceinline__ float mask_neg(const void* maskp, int mm, int idx) {
    if (mm == 0) return ((const int*)maskp)[idx] ? -1e20f : 0.0f;
    if (mm == 1) return ((const unsigned char*)maskp)[idx] ? -1e20f : 0.0f;
    return (((const float*)maskp)[idx] != 0.0f) ? -1e20f : 0.0f;
}

// ---------------- simple copy / zero ----------------
__global__ void copy_kernel(const float* __restrict__ src, float* __restrict__ dst, int n) {
    int i = blockIdx.x * blockDim.x + threadIdx.x;
    if (i < n) dst[i] = src[i];
}
__global__ void zero_kernel(float* __restrict__ dst, int n) {
    int i = blockIdx.x * blockDim.x + threadIdx.x;
    if (i < n) dst[i] = 0.0f;
}

// ---------------- SGEMM v2: 64x64 tile, BK=16, double-buffered, modes ----------------
// mode 0: single GEMM (z==0). mode 1: QKV (z selects B/C of 3). mode 2: split-K
// (z selects K-chunk; atomicAdd into pre-zeroed C).
__global__ __launch_bounds__(256) void sgemm2(
    const float* __restrict__ A,
    const float* __restrict__ B0, const float* __restrict__ B1, const float* __restrict__ B2,
    float* __restrict__ C0, float* __restrict__ C1, float* __restrict__ C2,
    int M, int N, int K,
    const float* __restrict__ bias, int dorelu, int mode, int nsplit)
{
    __shared__ float As[2][64][17];
    __shared__ float Bs[2][16][64];
    int t = threadIdx.x;
    int tx = t & 15, ty = t >> 4;
    int m0 = blockIdx.y * 64, n0 = blockIdx.x * 64;
    int z = blockIdx.z;

    const float* Bm = B0;
    float* C = C0;
    int Kc = K, k0 = 0, doatomic = 0;
    if (mode == 1) {
        Bm = (z == 0) ? B0 : (z == 1) ? B1 : B2;
        C  = (z == 0) ? C0 : (z == 1) ? C1 : C2;
    } else if (mode == 2) {
        Kc = K / nsplit;
        k0 = z * Kc;
        doatomic = 1;
    }

    int arow = t >> 2, acol = (t & 3) * 4;
    int brow = t >> 4, bcol = (t & 15) * 4;
    const float* Aptr = A + (m0 + arow) * K + k0 + acol;
    const float* Bptr = Bm + (k0 + brow) * N + n0 + bcol;

    float4 av = *(const float4*)Aptr;
    float4 bv = *(const float4*)Bptr;
    As[0][arow][acol + 0] = av.x; As[0][arow][acol + 1] = av.y;
    As[0][arow][acol + 2] = av.z; As[0][arow][acol + 3] = av.w;
    *(float4*)&Bs[0][brow][bcol] = bv;
    __syncthreads();

    float acc[4][4] = {};
    int nk = Kc / 16;
    int buf = 0;
    for (int kb = 0; kb < nk; kb++) {
        if (kb + 1 < nk) {
            av = *(const float4*)(Aptr + (kb + 1) * 16);
            bv = *(const float4*)(Bptr + (size_t)(kb + 1) * 16 * N);
        }
#pragma unroll
        for (int k2 = 0; k2 < 16; k2++) {
            float a0 = As[buf][ty * 4 + 0][k2];
            float a1 = As[buf][ty * 4 + 1][k2];
            float a2 = As[buf][ty * 4 + 2][k2];
            float a3 = As[buf][ty * 4 + 3][k2];
            float4 b4 = *(float4*)&Bs[buf][k2][tx * 4];
            acc[0][0] += a0 * b4.x; acc[0][1] += a0 * b4.y; acc[0][2] += a0 * b4.z; acc[0][3] += a0 * b4.w;
            acc[1][0] += a1 * b4.x; acc[1][1] += a1 * b4.y; acc[1][2] += a1 * b4.z; acc[1][3] += a1 * b4.w;
            acc[2][0] += a2 * b4.x; acc[2][1] += a2 * b4.y; acc[2][2] += a2 * b4.z; acc[2][3] += a2 * b4.w;
            acc[3][0] += a3 * b4.x; acc[3][1] += a3 * b4.y; acc[3][2] += a3 * b4.z; acc[3][3] += a3 * b4.w;
        }
        if (kb + 1 < nk) {
            int nb = buf ^ 1;
            As[nb][arow][acol + 0] = av.x; As[nb][arow][acol + 1] = av.y;
            As[nb][arow][acol + 2] = av.z; As[nb][arow][acol + 3] = av.w;
            *(float4*)&Bs[nb][brow][bcol] = bv;
            __syncthreads();
            buf = nb;
        }
    }

    int c0 = n0 + tx * 4;
    if (doatomic) {
#pragma unroll
        for (int i = 0; i < 4; i++) {
            int r = m0 + ty * 4 + i;
#pragma unroll
            for (int jj = 0; jj < 4; jj++)
                atomicAdd(&C[(size_t)r * N + c0 + jj], acc[i][jj]);
        }
    } else {
#pragma unroll
        for (int i = 0; i < 4; i++) {
            int r = m0 + ty * 4 + i;
            float4 o;
            o.x = acc[i][0]; o.y = acc[i][1]; o.z = acc[i][2]; o.w = acc[i][3];
            if (dorelu) {
                o.x = fmaxf(o.x + bias[c0 + 0], 0.0f);
                o.y = fmaxf(o.y + bias[c0 + 1], 0.0f);
                o.z = fmaxf(o.z + bias[c0 + 2], 0.0f);
                o.w = fmaxf(o.w + bias[c0 + 3], 0.0f);
            }
            *(float4*)&C[(size_t)r * N + c0] = o;
        }
    }
}

// ---------------- qrel: qrel[m, r] = sum_d q[m*32+d] * Ek[r*32+d] ----------------
__global__ __launch_bounds__(256) void qrel_kernel(
    const float* __restrict__ q, const float* __restrict__ Ek, float* __restrict__ qrel)
{
    __shared__ float Eks[REL_ * 33];
    __shared__ float qsm[64 * 32];
    int t = threadIdx.x;
    int r0 = blockIdx.x * 64;
    for (int idx = t; idx < REL_ * 32; idx += 256) {
        int r = idx >> 5, d = idx & 31;
        Eks[r * 33 + d] = Ek[idx];
    }
    for (int idx = t; idx < 64 * 32; idx += 256) qsm[idx] = q[r0 * 32 + idx];
    __syncthreads();
    for (int o = t; o < 64 * REL_; o += 256) {
        int i = o / REL_, r = o % REL_;
        float s = 0.0f;
#pragma unroll 8
        for (int d = 0; d < 32; d++) s += qsm[i * 32 + d] * Eks[r * 33 + d];
        qrel[(r0 + i) * REL_ + r] = s;
    }
}

// ---------------- fused flash attention + relation terms ----------------
// grid (L/16, NH, B), 256 threads. Online softmax, unnormalized o/arel accums.
// smem layout (floats):
#define A_KT   0                         // 128*33 = 4224
#define A_VT   (A_KT + 128 * 33)         // 128*32 = 4096
#define A_QT   (A_VT + 128 * 32)         // 32*16  = 512   (transposed q)
#define A_QR   (A_QT + 512)              // 16*100 = 1600
#define A_ARL  (A_QR + 1600)             // 16*100 = 1600
#define A_SC   (A_ARL + 1600)            // 16*132 = 2112
#define A_OH   (A_SC + 2112)             // 16*32  = 512   (half-1 partial o)
#define A_MS   (A_OH + 512)              // 16
#define A_SS   (A_MS + 16)               // 16
#define A_FC   (A_SS + 16)               // 16
#define A_RL   (A_FC + 16)               // 512 floats as 2048 uchar
#define ATTN_SMEM ((A_RL + 512) * 4)

__global__ __launch_bounds__(256) void attn_kernel(
    const float* __restrict__ q, const float* __restrict__ k,
    const float* __restrict__ v, const float* __restrict__ qrel,
    const int* __restrict__ rel, const void* __restrict__ maskp,
    const float* __restrict__ Ev, float* __restrict__ out)
{
    extern __shared__ float sm[];
    float* kt  = sm + A_KT;
    float* vt  = sm + A_VT;
    float* qt  = sm + A_QT;
    float* qr  = sm + A_QR;
    float* arl = sm + A_ARL;
    float* sc  = sm + A_SC;
    float* oh  = sm + A_OH;
    float* m_s = sm + A_MS;
    float* s_s = sm + A_SS;
    float* fac = sm + A_FC;
    unsigned char* rl = (unsigned char*)(sm + A_RL);

    int t = threadIdx.x;
    int w = t >> 5, l = t & 31;
    int i0 = blockIdx.x * 16, h = blockIdx.y, b = blockIdx.z;
    int mm = g_mask_mode;

    // prolog: q (transposed), qrel, init stats/bins
    for (int idx = t; idx < 16 * 32; idx += 256) {
        int i = idx >> 5, d = idx & 31;
        qt[d * 16 + i] = q[(b * L_ + i0 + i) * H_ + h * 32 + d];
    }
    for (int idx = t; idx < 16 * REL_; idx += 256) {
        int i = idx / REL_, r = idx % REL_;
        qr[idx] = qrel[(size_t)((b * L_ + i0 + i) * NH_ + h) * REL_ + r];
    }
    for (int idx = t; idx < 16 * REL_; idx += 256) arl[idx] = 0.0f;
    if (t < 16) { m_s[t] = -3.4e38f; s_s[t] = 0.0f; }

    int ia = 2 * w, ib = ia + 1;
    // o accumulators: half-split over j; thread owns (row, 4 dims)
    int half = t >> 7;
    int orow = (t >> 3) & 15;
    int od0 = (t & 7) * 4;
    float o0 = 0.f, o1 = 0.f, o2 = 0.f, o3 = 0.f;

    for (int jt = 0; jt < 8; jt++) {
        int j0 = jt * 128;
        __syncthreads();   // protect kt/vt/sc from previous-iter consumers
        for (int idx = t; idx < 128 * 32; idx += 256) {
            int j = idx >> 5, d = idx & 31;
            kt[j * 33 + d] = k[(b * L_ + j0 + j) * H_ + h * 32 + d];
        }
        for (int idx = t; idx < 128 * 32; idx += 256) {
            int j = idx >> 5, d = idx & 31;
            vt[j * 32 + d] = v[(b * L_ + j0 + j) * H_ + h * 32 + d];
        }
        __syncthreads();

        // ---- scores: warp w computes rows ia,ib, cols l+32c ----
        float acc[2][4] = {};
#pragma unroll 4
        for (int d = 0; d < 32; d++) {
            float2 qp = *(float2*)&qt[d * 16 + ia];
#pragma unroll
            for (int c = 0; c < 4; c++) {
                float kv = kt[(l + 32 * c) * 33 + d];
                acc[0][c] += qp.x * kv;
                acc[1][c] += qp.y * kv;
            }
        }
#pragma unroll
        for (int c = 0; c < 4; c++) {
            int j = l + 32 * c;
            int ga = (b * L_ + i0 + ia) * L_ + j0 + j;
            int gb = (b * L_ + i0 + ib) * L_ + j0 + j;
            int ra = rel[ga], rb = rel[gb];
            float na = mask_neg(maskp, mm, ga);
            float nb = mask_neg(maskp, mm, gb);
            sc[ia * 132 + j] = (acc[0][c] + qr[ia * REL_ + ra]) * INV_SCALE + na;
            sc[ib * 132 + j] = (acc[1][c] + qr[ib * REL_ + rb]) * INV_SCALE + nb;
            rl[ia * 128 + j] = (unsigned char)ra;
            rl[ib * 128 + j] = (unsigned char)rb;
        }
        // (no sync: rows ia/ib consumed by same warp below)

        // ---- online softmax + bin rescale + binning (warp-local rows) ----
#pragma unroll
        for (int rr = 0; rr < 2; rr++) {
            int i = ia + rr;
            float mx = -3.4e38f;
#pragma unroll
            for (int c = 0; c < 4; c++) mx = fmaxf(mx, sc[i * 132 + l + 32 * c]);
#pragma unroll
            for (int off = 16; off; off >>= 1) mx = fmaxf(mx, __shfl_xor_sync(0xffffffffu, mx, off));
            float m_old = m_s[i];
            float m_new = fmaxf(m_old, mx);
            float f = __expf(m_old - m_new);
            float ssum = 0.0f;
#pragma unroll
            for (int c = 0; c < 4; c++) {
                int j = l + 32 * c;
                float p = __expf(sc[i * 132 + j] - m_new);
                sc[i * 132 + j] = p;
                ssum += p;
            }
#pragma unroll
            for (int off = 16; off; off >>= 1) ssum += __shfl_xor_sync(0xffffffffu, ssum, off);
            if (l == 0) { m_s[i] = m_new; s_s[i] = s_s[i] * f + ssum; fac[i] = f; }
            for (int r = l; r < REL_; r += 32) arl[i * REL_ + r] *= f;
        }
        __syncwarp();
        // binning: 8 entries per lane, rows ia/ib
#pragma unroll
        for (int c = 0; c < 8; c++) {
            int i = ia + (c >> 2);
            int j = l + 32 * (c & 3);
            float p = sc[i * 132 + j];
            if (p != 0.0f) atomicAdd(&arl[i * REL_ + rl[i * 128 + j]], p);
        }
        __syncthreads();   // fac[] + all rows' p visible

        // ---- o accumulate: thread (orow, od0..od0+3), j in its half ----
        float f2 = fac[orow];
        o0 *= f2; o1 *= f2; o2 *= f2; o3 *= f2;
        int jlo = half * 64;
#pragma unroll 8
        for (int j = jlo; j < jlo + 64; j++) {
            float p = sc[orow * 132 + j];
            float4 v4 = *(float4*)&vt[j * 32 + od0];
            o0 += p * v4.x; o1 += p * v4.y; o2 += p * v4.z; o3 += p * v4.w;
        }
    }

    // ---- epilogue: combine halves, add relation-value, normalize ----
    __syncthreads();
    if (half) {
        float4 o4; o4.x = o0; o4.y = o1; o4.z = o2; o4.w = o3;
        *(float4*)&oh[orow * 32 + od0] = o4;
    }
    __syncthreads();
    if (!half) {
        float4 ph = *(float4*)&oh[orow * 32 + od0];
        o0 += ph.x; o1 += ph.y; o2 += ph.z; o3 += ph.w;
#pragma unroll 4
        for (int r = 0; r < REL_; r++) {
            float wv = arl[orow * REL_ + r];
            float4 e = *(const float4*)&Ev[r * 32 + od0];
            o0 += wv * e.x; o1 += wv * e.y; o2 += wv * e.z; o3 += wv * e.w;
        }
        float inv = 1.0f / s_s[orow];
        float4 o4;
        o4.x = o0 * inv; o4.y = o1 * inv; o4.z = o2 * inv; o4.w = o3 * inv;
        *(float4*)&out[(b * L_ + i0 + orow) * H_ + h * 32 + od0] = o4;
    }
}

// ---------------- bias + residual + LayerNorm (row per CTA, H=256) ----------------
__global__ __launch_bounds__(256) void ln_kernel(
    const float* __restrict__ tin, const float* __restrict__ bias,
    const float* __restrict__ resid, const float* __restrict__ gam,
    const float* __restrict__ bet, float* __restrict__ out)
{
    int row = blockIdx.x, c = threadIdx.x;
    float vv = tin[row * H_ + c] + bias[c] + resid[row * H_ + c];
    __shared__ float red[16];
    float s1 = vv, s2 = vv * vv;
#pragma unroll
    for (int off = 16; off; off >>= 1) {
        s1 += __shfl_xor_sync(0xffffffffu, s1, off);
        s2 += __shfl_xor_sync(0xffffffffu, s2, off);
    }
    int w = c >> 5, l = c & 31;
    if (l == 0) { red[w] = s1; red[8 + w] = s2; }
    __syncthreads();
    float t1 = 0.0f, t2 = 0.0f;
#pragma unroll
    for (int ww = 0; ww < 8; ww++) { t1 += red[ww]; t2 += red[8 + ww]; }
    float mean = t1 * (1.0f / 256.0f);
    float var = t2 * (1.0f / 256.0f) - mean * mean;
    out[row * H_ + c] = (vv - mean) * rsqrtf(var + EPS_) * gam[c] + bet[c];
}

// ---------------- launch ----------------
extern "C" void kernel_launch(void* const* d_in, const int* in_sizes, int n_in,
                              void* d_out, int out_size)
{
    (void)in_sizes; (void)n_in; (void)out_size;
    const float* inputs = (const float*)d_in[0];
    const float* Wq = (const float*)d_in[1];
    const float* Wk = (const float*)d_in[2];
    const float* Wv = (const float*)d_in[3];
    const float* Wo = (const float*)d_in[4];
    const float* bo = (const float*)d_in[5];
    const float* W1 = (const float*)d_in[6];
    const float* b1 = (const float*)d_in[7];
    const float* W2 = (const float*)d_in[8];
    const float* b2 = (const float*)d_in[9];
    const float* ln1g = (const float*)d_in[10];
    const float* ln1b = (const float*)d_in[11];
    const float* ln2g = (const float*)d_in[12];
    const float* ln2b = (const float*)d_in[13];
    const float* Ek = (const float*)d_in[14];
    const float* Ev = (const float*)d_in[15];
    const int*   rel = (const int*)d_in[16];
    const void*  mask = d_in[17];

    float *px, *pq, *pk, *pv, *pqr, *pao, *ptmp, *pffh;
    cudaGetSymbolAddress((void**)&px,  g_x);
    cudaGetSymbolAddress((void**)&pq,  g_q);
    cudaGetSymbolAddress((void**)&pk,  g_k);
    cudaGetSymbolAddress((void**)&pv,  g_v);
    cudaGetSymbolAddress((void**)&pqr, g_qrel);
    cudaGetSymbolAddress((void**)&pao, g_ao);
    cudaGetSymbolAddress((void**)&ptmp, g_tmp);
    cudaGetSymbolAddress((void**)&pffh, g_ffh);

    cudaFuncSetAttribute(attn_kernel, cudaFuncAttributeMaxDynamicSharedMemorySize, ATTN_SMEM);

    detect_mask_kernel<<<1, 1>>>((const unsigned char*)mask);
    copy_kernel<<<(M_ * H_ + 255) / 256, 256>>>(inputs, px, M_ * H_);

    for (int l = 0; l < NL_; l++) {
        const float* wq = Wq + l * H_ * H_;
        const float* wk = Wk + l * H_ * H_;
        const float* wv = Wv + l * H_ * H_;
        const float* wo = Wo + l * H_ * H_;
        const float* w1 = W1 + l * H_ * FF_;
        const float* w2 = W2 + l * FF_ * H_;

        // fused QKV (one launch, 384 CTAs)
        sgemm2<<<dim3(H_ / 64, M_ / 64, 3), 256>>>(
            px, wq, wk, wv, pq, pk, pv, M_, H_, H_, nullptr, 0, 1, 1);

        qrel_kernel<<<(M_ * NH_) / 64, 256>>>(pq, Ek, pqr);

        attn_kernel<<<dim3(L_ / 16, NH_, B_), 256, ATTN_SMEM>>>(
            pq, pk, pv, pqr, rel, mask, Ev, pao);

        // Wo: split-K=2 into zeroed tmp
        zero_kernel<<<(M_ * H_ + 255) / 256, 256>>>(ptmp, M_ * H_);
        sgemm2<<<dim3(H_ / 64, M_ / 64, 2), 256>>>(
            pao, wo, nullptr, nullptr, ptmp, nullptr, nullptr, M_, H_, H_, nullptr, 0, 2, 2);

        ln_kernel<<<M_, 256>>>(ptmp, bo + l * H_, px, ln1g + l * H_, ln1b + l * H_, px);

        // FF1: bias + relu fused
        sgemm2<<<dim3(FF_ / 64, M_ / 64, 1), 256>>>(
            px, w1, nullptr, nullptr, pffh, nullptr, nullptr, M_, FF_, H_, b1 + l * FF_, 1, 0, 1);

        // FF2: split-K=4 into zeroed tmp
        zero_kernel<<<(M_ * H_ + 255) / 256, 256>>>(ptmp, M_ * H_);
        sgemm2<<<dim3(H_ / 64, M_ / 64, 4), 256>>>(
            pffh, w2, nullptr, nullptr, ptmp, nullptr, nullptr, M_, H_, FF_, nullptr, 0, 2, 4);

        float* dst = (l == NL_ - 1) ? (float*)d_out : px;
        ln_kernel<<<M_, 256>>>(ptmp, b2 + l * H_, px, ln2g + l * H_, ln2b + l * H_, dst);
    }
}

// round 4
// speedup vs baseline: 1.4887x; 1.1087x over previous
#include <cuda_runtime.h>
#include <cuda_bf16.h>
#include <math.h>

// Problem constants
#define B_ 2
#define L_ 1024
#define H_ 256
#define NH_ 8
#define DH_ 32
#define FF_ 1024
#define NL_ 2
#define REL_ 100
#define M_ (B_ * L_)            // 2048 rows
#define INV_SCALE 0.17677669529663687f   // 1/sqrt(32)
#define EPS_ 1e-5f

// ---------------- scratch (device globals; no runtime alloc) ----------------
__device__ float g_x[M_ * H_];
__device__ float g_q[M_ * H_];
__device__ float g_k[M_ * H_];
__device__ float g_v[M_ * H_];
__device__ float g_ao[M_ * H_];
__device__ float g_tmp[M_ * H_];
__device__ float g_ffh[M_ * FF_];
__device__ int   g_mask_mode;                 // 0=int32, 1=uint8, 2=float32

// ---------------- mask dtype detection (deterministic) ----------------
__global__ void detect_mask_kernel(const unsigned char* __restrict__ m) {
    if (threadIdx.x == 0 && blockIdx.x == 0) {
        bool nz12 = false, nz3 = false;
        for (int i = 0; i < 16384; i++) {
            unsigned char v = m[i];
            if (v) {
                int o = i & 3;
                if (o == 1 || o == 2) nz12 = true;
                else if (o == 3) nz3 = true;
            }
        }
        g_mask_mode = nz12 ? 1 : (nz3 ? 2 : 0);
    }
}

__device__ __forceinline__ float mask_neg(const void* maskp, int mm, int idx) {
    if (mm == 0) return ((const int*)maskp)[idx] ? -1e20f : 0.0f;
    if (mm == 1) return ((const unsigned char*)maskp)[idx] ? -1e20f : 0.0f;
    return (((const float*)maskp)[idx] != 0.0f) ? -1e20f : 0.0f;
}

// ---------------- simple copy / zero ----------------
__global__ void copy_kernel(const float* __restrict__ src, float* __restrict__ dst, int n) {
    int i = blockIdx.x * blockDim.x + threadIdx.x;
    if (i < n) dst[i] = src[i];
}
__global__ void zero_kernel(float* __restrict__ dst, int n) {
    int i = blockIdx.x * blockDim.x + threadIdx.x;
    if (i < n) dst[i] = 0.0f;
}

// ---------------- SGEMM v2: 64x64 tile, BK=16, double-buffered, modes ----------------
// mode 0: single GEMM. mode 1: QKV (z selects B/C of 3). mode 2: split-K
// (z selects K-chunk; atomicAdd into pre-zeroed C).
__global__ __launch_bounds__(256) void sgemm2(
    const float* __restrict__ A,
    const float* __restrict__ B0, const float* __restrict__ B1, const float* __restrict__ B2,
    float* __restrict__ C0, float* __restrict__ C1, float* __restrict__ C2,
    int M, int N, int K,
    const float* __restrict__ bias, int dorelu, int mode, int nsplit)
{
    __shared__ float As[2][64][17];
    __shared__ float Bs[2][16][64];
    int t = threadIdx.x;
    int tx = t & 15, ty = t >> 4;
    int m0 = blockIdx.y * 64, n0 = blockIdx.x * 64;
    int z = blockIdx.z;

    const float* Bm = B0;
    float* C = C0;
    int Kc = K, k0 = 0, doatomic = 0;
    if (mode == 1) {
        Bm = (z == 0) ? B0 : (z == 1) ? B1 : B2;
        C  = (z == 0) ? C0 : (z == 1) ? C1 : C2;
    } else if (mode == 2) {
        Kc = K / nsplit;
        k0 = z * Kc;
        doatomic = 1;
    }

    int arow = t >> 2, acol = (t & 3) * 4;
    int brow = t >> 4, bcol = (t & 15) * 4;
    const float* Aptr = A + (m0 + arow) * K + k0 + acol;
    const float* Bptr = Bm + (k0 + brow) * N + n0 + bcol;

    float4 av = *(const float4*)Aptr;
    float4 bv = *(const float4*)Bptr;
    As[0][arow][acol + 0] = av.x; As[0][arow][acol + 1] = av.y;
    As[0][arow][acol + 2] = av.z; As[0][arow][acol + 3] = av.w;
    *(float4*)&Bs[0][brow][bcol] = bv;
    __syncthreads();

    float acc[4][4] = {};
    int nk = Kc / 16;
    int buf = 0;
    for (int kb = 0; kb < nk; kb++) {
        if (kb + 1 < nk) {
            av = *(const float4*)(Aptr + (kb + 1) * 16);
            bv = *(const float4*)(Bptr + (size_t)(kb + 1) * 16 * N);
        }
#pragma unroll
        for (int k2 = 0; k2 < 16; k2++) {
            float a0 = As[buf][ty * 4 + 0][k2];
            float a1 = As[buf][ty * 4 + 1][k2];
            float a2 = As[buf][ty * 4 + 2][k2];
            float a3 = As[buf][ty * 4 + 3][k2];
            float4 b4 = *(float4*)&Bs[buf][k2][tx * 4];
            acc[0][0] += a0 * b4.x; acc[0][1] += a0 * b4.y; acc[0][2] += a0 * b4.z; acc[0][3] += a0 * b4.w;
            acc[1][0] += a1 * b4.x; acc[1][1] += a1 * b4.y; acc[1][2] += a1 * b4.z; acc[1][3] += a1 * b4.w;
            acc[2][0] += a2 * b4.x; acc[2][1] += a2 * b4.y; acc[2][2] += a2 * b4.z; acc[2][3] += a2 * b4.w;
            acc[3][0] += a3 * b4.x; acc[3][1] += a3 * b4.y; acc[3][2] += a3 * b4.z; acc[3][3] += a3 * b4.w;
        }
        if (kb + 1 < nk) {
            int nb = buf ^ 1;
            As[nb][arow][acol + 0] = av.x; As[nb][arow][acol + 1] = av.y;
            As[nb][arow][acol + 2] = av.z; As[nb][arow][acol + 3] = av.w;
            *(float4*)&Bs[nb][brow][bcol] = bv;
            __syncthreads();
            buf = nb;
        }
    }

    int c0 = n0 + tx * 4;
    if (doatomic) {
#pragma unroll
        for (int i = 0; i < 4; i++) {
            int r = m0 + ty * 4 + i;
#pragma unroll
            for (int jj = 0; jj < 4; jj++)
                atomicAdd(&C[(size_t)r * N + c0 + jj], acc[i][jj]);
        }
    } else {
#pragma unroll
        for (int i = 0; i < 4; i++) {
            int r = m0 + ty * 4 + i;
            float4 o;
            o.x = acc[i][0]; o.y = acc[i][1]; o.z = acc[i][2]; o.w = acc[i][3];
            if (dorelu) {
                o.x = fmaxf(o.x + bias[c0 + 0], 0.0f);
                o.y = fmaxf(o.y + bias[c0 + 1], 0.0f);
                o.z = fmaxf(o.z + bias[c0 + 2], 0.0f);
                o.w = fmaxf(o.w + bias[c0 + 3], 0.0f);
            }
            *(float4*)&C[(size_t)r * N + c0] = o;
        }
    }
}

// ---------------- fused flash attention v2: 32-row q tile ----------------
// grid (L/32, NH, B), 256 threads.
// kt/vt use XOR swizzle: float4 slot = j*8 + (d4 ^ (j&7))  -> conflict-free LDS.128.
// smem float offsets:
#define A2_KT   0                           // 4096 (also Ek staging / Ev staging)
#define A2_VT   (A2_KT + 4096)              // 4096
#define A2_QS   (A2_VT + 4096)              // 32*36 = 1152
#define A2_QR   (A2_QS + 1152)              // 32*100 = 3200
#define A2_ARL  (A2_QR + 3200)              // 32*100 = 3200
#define A2_SC   (A2_ARL + 3200)             // 32*132 = 4224
#define A2_OH   (A2_SC + 4224)              // 3*64*16 = 3072
#define A2_RL   (A2_OH + 3072)              // 1024 floats = 4096 uchar
#define A2_MS   (A2_RL + 1024)              // 32
#define A2_SS   (A2_MS + 32)                // 32
#define A2_FC   (A2_SS + 32)                // 32
#define ATTN2_SMEM ((A2_FC + 32) * 4)       // 96,640 B

__global__ __launch_bounds__(256) void attn2_kernel(
    const float* __restrict__ q, const float* __restrict__ k,
    const float* __restrict__ v, const float* __restrict__ Ek,
    const int* __restrict__ rel, const void* __restrict__ maskp,
    const float* __restrict__ Ev, float* __restrict__ out)
{
    extern __shared__ float sm[];
    float* kt  = sm + A2_KT;
    float* vt  = sm + A2_VT;
    float* qs  = sm + A2_QS;
    float* qr  = sm + A2_QR;
    float* arl = sm + A2_ARL;
    float* sc  = sm + A2_SC;
    float* oh  = sm + A2_OH;
    float* m_s = sm + A2_MS;
    float* s_s = sm + A2_SS;
    float* fac = sm + A2_FC;
    unsigned char* rl = (unsigned char*)(sm + A2_RL);
    float4* kt4 = (float4*)kt;
    float4* vt4 = (float4*)vt;

    int t = threadIdx.x;
    int w = t >> 5, l = t & 31;
    int i0 = blockIdx.x * 32, h = blockIdx.y, b = blockIdx.z;
    int mm = g_mask_mode;

    // ---- prolog: q rows, Ek->kt staging, qrel compute, init ----
    for (int idx = t; idx < 32 * 32; idx += 256) {
        int i = idx >> 5, d = idx & 31;
        qs[i * 36 + d] = q[(b * L_ + i0 + i) * H_ + h * 32 + d];
    }
    for (int idx = t; idx < REL_ * 32; idx += 256) kt[idx] = Ek[idx];   // stride 32
    for (int idx = t; idx < 32 * REL_; idx += 256) arl[idx] = 0.0f;
    if (t < 32) { m_s[t] = -3.4e38f; s_s[t] = 0.0f; }
    __syncthreads();

    {   // qr[i][r] = sum_d qs[i][d] * Ek[r][d]; thread: row i = t>>3, lane8 = t&7
        int i = t >> 3, l8 = t & 7;
        for (int quad = l8; quad < 25; quad += 8) {
            float a0 = 0.f, a1 = 0.f, a2 = 0.f, a3 = 0.f;
#pragma unroll
            for (int d4 = 0; d4 < 8; d4++) {
                float4 qv = *(float4*)&qs[i * 36 + d4 * 4];
                float4 e0 = *(float4*)&kt[(quad * 4 + 0) * 32 + d4 * 4];
                float4 e1 = *(float4*)&kt[(quad * 4 + 1) * 32 + d4 * 4];
                float4 e2 = *(float4*)&kt[(quad * 4 + 2) * 32 + d4 * 4];
                float4 e3 = *(float4*)&kt[(quad * 4 + 3) * 32 + d4 * 4];
                a0 += qv.x * e0.x + qv.y * e0.y + qv.z * e0.z + qv.w * e0.w;
                a1 += qv.x * e1.x + qv.y * e1.y + qv.z * e1.z + qv.w * e1.w;
                a2 += qv.x * e2.x + qv.y * e2.y + qv.z * e2.z + qv.w * e2.w;
                a3 += qv.x * e3.x + qv.y * e3.y + qv.z * e3.z + qv.w * e3.w;
            }
            qr[i * REL_ + quad * 4 + 0] = a0;
            qr[i * REL_ + quad * 4 + 1] = a1;
            qr[i * REL_ + quad * 4 + 2] = a2;
            qr[i * REL_ + quad * 4 + 3] = a3;
        }
    }

    // AV-thread decomposition: t = jq*64 + rp8*8 + d4i
    int jq  = t >> 6;          // j-quarter 0..3
    int rp8 = (t >> 3) & 7;    // row group: rows rp8 + 8k
    int d4i = t & 7;           // dim quad
    float4 o[4];
#pragma unroll
    for (int k4 = 0; k4 < 4; k4++) { o[k4].x = 0.f; o[k4].y = 0.f; o[k4].z = 0.f; o[k4].w = 0.f; }

    int r0 = w * 4;            // scores: warp w owns rows r0..r0+3

    const float4* kg = (const float4*)(k + (size_t)(b * L_) * H_ + h * 32);
    const float4* vg = (const float4*)(v + (size_t)(b * L_) * H_ + h * 32);

    for (int jt = 0; jt < 8; jt++) {
        int j0 = jt * 128;
        __syncthreads();   // protect kt/vt/sc (also fences prolog's Ek use at jt==0)
        // ---- fill k/v tiles (swizzled) ----
        for (int idx = t; idx < 1024; idx += 256) {
            int j = idx >> 3, d4 = idx & 7;
            int slot = j * 8 + (d4 ^ (j & 7));
            kt4[slot] = kg[(size_t)(j0 + j) * 64 + d4];
            vt4[slot] = vg[(size_t)(j0 + j) * 64 + d4];
        }
        __syncthreads();

        // ---- scores: 4 rows x 4 cols per thread ----
        float acc[4][4] = {};
#pragma unroll
        for (int d4 = 0; d4 < 8; d4++) {
            float4 qv0 = *(float4*)&qs[(r0 + 0) * 36 + d4 * 4];
            float4 qv1 = *(float4*)&qs[(r0 + 1) * 36 + d4 * 4];
            float4 qv2 = *(float4*)&qs[(r0 + 2) * 36 + d4 * 4];
            float4 qv3 = *(float4*)&qs[(r0 + 3) * 36 + d4 * 4];
#pragma unroll
            for (int c = 0; c < 4; c++) {
                int j = l + 32 * c;
                float4 kv = kt4[j * 8 + (d4 ^ (j & 7))];
                acc[0][c] += qv0.x * kv.x + qv0.y * kv.y + qv0.z * kv.z + qv0.w * kv.w;
                acc[1][c] += qv1.x * kv.x + qv1.y * kv.y + qv1.z * kv.z + qv1.w * kv.w;
                acc[2][c] += qv2.x * kv.x + qv2.y * kv.y + qv2.z * kv.z + qv2.w * kv.w;
                acc[3][c] += qv3.x * kv.x + qv3.y * kv.y + qv3.z * kv.z + qv3.w * kv.w;
            }
        }
#pragma unroll
        for (int rr = 0; rr < 4; rr++) {
            int i = r0 + rr;
#pragma unroll
            for (int c = 0; c < 4; c++) {
                int j = l + 32 * c;
                int g = (b * L_ + i0 + i) * L_ + j0 + j;
                int rid = rel[g];
                float nm = mask_neg(maskp, mm, g);
                sc[i * 132 + j] = (acc[rr][c] + qr[i * REL_ + rid]) * INV_SCALE + nm;
                rl[i * 128 + j] = (unsigned char)rid;
            }
        }

        // ---- online softmax (warp-local rows) ----
#pragma unroll
        for (int rr = 0; rr < 4; rr++) {
            int i = r0 + rr;
            float mx = -3.4e38f;
#pragma unroll
            for (int c = 0; c < 4; c++) mx = fmaxf(mx, sc[i * 132 + l + 32 * c]);
#pragma unroll
            for (int off = 16; off; off >>= 1) mx = fmaxf(mx, __shfl_xor_sync(0xffffffffu, mx, off));
            float m_old = m_s[i];
            float m_new = fmaxf(m_old, mx);
            float f = __expf(m_old - m_new);
            float ssum = 0.0f;
#pragma unroll
            for (int c = 0; c < 4; c++) {
                int j = l + 32 * c;
                float p = __expf(sc[i * 132 + j] - m_new);
                sc[i * 132 + j] = p;
                ssum += p;
            }
#pragma unroll
            for (int off = 16; off; off >>= 1) ssum += __shfl_xor_sync(0xffffffffu, ssum, off);
            if (l == 0) { m_s[i] = m_new; s_s[i] = s_s[i] * f + ssum; fac[i] = f; }
            for (int r = l; r < REL_; r += 32) arl[i * REL_ + r] *= f;
        }
        __syncwarp();
        // ---- binning ----
#pragma unroll
        for (int rr = 0; rr < 4; rr++) {
            int i = r0 + rr;
#pragma unroll
            for (int c = 0; c < 4; c++) {
                int j = l + 32 * c;
                float p = sc[i * 132 + j];
                if (p != 0.0f) atomicAdd(&arl[i * REL_ + rl[i * 128 + j]], p);
            }
        }
        __syncthreads();   // fac + all probs visible

        // ---- AV: 4 rows x 4 dims x quarter-j per thread ----
        float f0 = fac[rp8 + 0], f1 = fac[rp8 + 8], f2 = fac[rp8 + 16], f3 = fac[rp8 + 24];
        o[0].x *= f0; o[0].y *= f0; o[0].z *= f0; o[0].w *= f0;
        o[1].x *= f1; o[1].y *= f1; o[1].z *= f1; o[1].w *= f1;
        o[2].x *= f2; o[2].y *= f2; o[2].z *= f2; o[2].w *= f2;
        o[3].x *= f3; o[3].y *= f3; o[3].z *= f3; o[3].w *= f3;
        int jlo = jq * 32;
#pragma unroll 4
        for (int jj = 0; jj < 32; jj++) {
            int j = jlo + jj;
            float4 v4 = vt4[j * 8 + (d4i ^ (j & 7))];
            float p0 = sc[(rp8 + 0) * 132 + j];
            float p1 = sc[(rp8 + 8) * 132 + j];
            float p2 = sc[(rp8 + 16) * 132 + j];
            float p3 = sc[(rp8 + 24) * 132 + j];
            o[0].x += p0 * v4.x; o[0].y += p0 * v4.y; o[0].z += p0 * v4.z; o[0].w += p0 * v4.w;
            o[1].x += p1 * v4.x; o[1].y += p1 * v4.y; o[1].z += p1 * v4.z; o[1].w += p1 * v4.w;
            o[2].x += p2 * v4.x; o[2].y += p2 * v4.y; o[2].z += p2 * v4.z; o[2].w += p2 * v4.w;
            o[3].x += p3 * v4.x; o[3].y += p3 * v4.y; o[3].z += p3 * v4.z; o[3].w += p3 * v4.w;
        }
    }

    // ---- epilogue ----
    __syncthreads();
    // stage Ev into kt area
    for (int idx = t; idx < REL_ * 32; idx += 256) kt[idx] = Ev[idx];
    int slot = rp8 * 8 + d4i;
    if (jq > 0) {
        float4* dst = (float4*)&oh[((jq - 1) * 64 + slot) * 16];
#pragma unroll
        for (int k4 = 0; k4 < 4; k4++) dst[k4] = o[k4];
    }
    __syncthreads();
    if (jq == 0) {
#pragma unroll
        for (int qq = 0; qq < 3; qq++) {
            float4* src = (float4*)&oh[(qq * 64 + slot) * 16];
#pragma unroll
            for (int k4 = 0; k4 < 4; k4++) {
                float4 s4 = src[k4];
                o[k4].x += s4.x; o[k4].y += s4.y; o[k4].z += s4.z; o[k4].w += s4.w;
            }
        }
#pragma unroll 4
        for (int r = 0; r < REL_; r++) {
            float4 e = *(float4*)&kt[r * 32 + d4i * 4];
            float w0 = arl[(rp8 + 0) * REL_ + r];
            float w1 = arl[(rp8 + 8) * REL_ + r];
            float w2 = arl[(rp8 + 16) * REL_ + r];
            float w3 = arl[(rp8 + 24) * REL_ + r];
            o[0].x += w0 * e.x; o[0].y += w0 * e.y; o[0].z += w0 * e.z; o[0].w += w0 * e.w;
            o[1].x += w1 * e.x; o[1].y += w1 * e.y; o[1].z += w1 * e.z; o[1].w += w1 * e.w;
            o[2].x += w2 * e.x; o[2].y += w2 * e.y; o[2].z += w2 * e.z; o[2].w += w2 * e.w;
            o[3].x += w3 * e.x; o[3].y += w3 * e.y; o[3].z += w3 * e.z; o[3].w += w3 * e.w;
        }
#pragma unroll
        for (int k4 = 0; k4 < 4; k4++) {
            int r = rp8 + 8 * k4;
            float inv = 1.0f / s_s[r];
            float4 o4;
            o4.x = o[k4].x * inv; o4.y = o[k4].y * inv; o4.z = o[k4].z * inv; o4.w = o[k4].w * inv;
            *(float4*)&out[(size_t)(b * L_ + i0 + r) * H_ + h * 32 + d4i * 4] = o4;
        }
    }
}

// ---------------- bias + residual + LayerNorm (row per CTA, H=256) ----------------
__global__ __launch_bounds__(256) void ln_kernel(
    const float* __restrict__ tin, const float* __restrict__ bias,
    const float* __restrict__ resid, const float* __restrict__ gam,
    const float* __restrict__ bet, float* __restrict__ out)
{
    int row = blockIdx.x, c = threadIdx.x;
    float vv = tin[row * H_ + c] + bias[c] + resid[row * H_ + c];
    __shared__ float red[16];
    float s1 = vv, s2 = vv * vv;
#pragma unroll
    for (int off = 16; off; off >>= 1) {
        s1 += __shfl_xor_sync(0xffffffffu, s1, off);
        s2 += __shfl_xor_sync(0xffffffffu, s2, off);
    }
    int w = c >> 5, l = c & 31;
    if (l == 0) { red[w] = s1; red[8 + w] = s2; }
    __syncthreads();
    float t1 = 0.0f, t2 = 0.0f;
#pragma unroll
    for (int ww = 0; ww < 8; ww++) { t1 += red[ww]; t2 += red[8 + ww]; }
    float mean = t1 * (1.0f / 256.0f);
    float var = t2 * (1.0f / 256.0f) - mean * mean;
    out[row * H_ + c] = (vv - mean) * rsqrtf(var + EPS_) * gam[c] + bet[c];
}

// ---------------- launch ----------------
extern "C" void kernel_launch(void* const* d_in, const int* in_sizes, int n_in,
                              void* d_out, int out_size)
{
    (void)in_sizes; (void)n_in; (void)out_size;
    const float* inputs = (const float*)d_in[0];
    const float* Wq = (const float*)d_in[1];
    const float* Wk = (const float*)d_in[2];
    const float* Wv = (const float*)d_in[3];
    const float* Wo = (const float*)d_in[4];
    const float* bo = (const float*)d_in[5];
    const float* W1 = (const float*)d_in[6];
    const float* b1 = (const float*)d_in[7];
    const float* W2 = (const float*)d_in[8];
    const float* b2 = (const float*)d_in[9];
    const float* ln1g = (const float*)d_in[10];
    const float* ln1b = (const float*)d_in[11];
    const float* ln2g = (const float*)d_in[12];
    const float* ln2b = (const float*)d_in[13];
    const float* Ek = (const float*)d_in[14];
    const float* Ev = (const float*)d_in[15];
    const int*   rel = (const int*)d_in[16];
    const void*  mask = d_in[17];

    float *px, *pq, *pk, *pv, *pao, *ptmp, *pffh;
    cudaGetSymbolAddress((void**)&px,  g_x);
    cudaGetSymbolAddress((void**)&pq,  g_q);
    cudaGetSymbolAddress((void**)&pk,  g_k);
    cudaGetSymbolAddress((void**)&pv,  g_v);
    cudaGetSymbolAddress((void**)&pao, g_ao);
    cudaGetSymbolAddress((void**)&ptmp, g_tmp);
    cudaGetSymbolAddress((void**)&pffh, g_ffh);

    cudaFuncSetAttribute(attn2_kernel, cudaFuncAttributeMaxDynamicSharedMemorySize, ATTN2_SMEM);

    detect_mask_kernel<<<1, 1>>>((const unsigned char*)mask);
    copy_kernel<<<(M_ * H_ + 255) / 256, 256>>>(inputs, px, M_ * H_);

    for (int l = 0; l < NL_; l++) {
        const float* wq = Wq + l * H_ * H_;
        const float* wk = Wk + l * H_ * H_;
        const float* wv = Wv + l * H_ * H_;
        const float* wo = Wo + l * H_ * H_;
        const float* w1 = W1 + l * H_ * FF_;
        const float* w2 = W2 + l * FF_ * H_;

        // fused QKV (one launch, 384 CTAs)
        sgemm2<<<dim3(H_ / 64, M_ / 64, 3), 256>>>(
            px, wq, wk, wv, pq, pk, pv, M_, H_, H_, nullptr, 0, 1, 1);

        attn2_kernel<<<dim3(L_ / 32, NH_, B_), 256, ATTN2_SMEM>>>(
            pq, pk, pv, Ek, rel, mask, Ev, pao);

        // Wo: split-K=2 into zeroed tmp
        zero_kernel<<<(M_ * H_ + 255) / 256, 256>>>(ptmp, M_ * H_);
        sgemm2<<<dim3(H_ / 64, M_ / 64, 2), 256>>>(
            pao, wo, nullptr, nullptr, ptmp, nullptr, nullptr, M_, H_, H_, nullptr, 0, 2, 2);

        ln_kernel<<<M_, 256>>>(ptmp, bo + l * H_, px, ln1g + l * H_, ln1b + l * H_, px);

        // FF1: bias + relu fused
        sgemm2<<<dim3(FF_ / 64, M_ / 64, 1), 256>>>(
            px, w1, nullptr, nullptr, pffh, nullptr, nullptr, M_, FF_, H_, b1 + l * FF_, 1, 0, 1);

        // FF2: split-K=4 into zeroed tmp
        zero_kernel<<<(M_ * H_ + 255) / 256, 256>>>(ptmp, M_ * H_);
        sgemm2<<<dim3(H_ / 64, M_ / 64, 4), 256>>>(
            pffh, w2, nullptr, nullptr, ptmp, nullptr, nullptr, M_, H_, FF_, nullptr, 0, 2, 4);

        float* dst = (l == NL_ - 1) ? (float*)d_out : px;
        ln_kernel<<<M_, 256>>>(ptmp, b2 + l * H_, px, ln2g + l * H_, ln2b + l * H_, dst);
    }
}

// round 5
// speedup vs baseline: 1.5357x; 1.0316x over previous
#include <cuda_runtime.h>
#include <cuda_bf16.h>
#include <math.h>

// Problem constants
#define B_ 2
#define L_ 1024
#define H_ 256
#define NH_ 8
#define DH_ 32
#define FF_ 1024
#define NL_ 2
#define REL_ 100
#define M_ (B_ * L_)            // 2048 rows
#define INV_SCALE 0.17677669529663687f   // 1/sqrt(32)
#define EPS_ 1e-5f

// ---------------- scratch (device globals; no runtime alloc) ----------------
__device__ float g_x[M_ * H_];
__device__ float g_q[M_ * H_];
__device__ float g_k[M_ * H_];
__device__ float g_v[M_ * H_];
__device__ float g_ao[M_ * H_];
__device__ float g_tmp[4 * M_ * H_];          // up to 4 split-K partial buffers
__device__ float g_ffh[M_ * FF_];
__device__ int   g_mask_mode;                 // 0=int32, 1=uint8, 2=float32

// ---------------- mask dtype detection (deterministic) ----------------
__global__ void detect_mask_kernel(const unsigned char* __restrict__ m) {
    if (threadIdx.x == 0 && blockIdx.x == 0) {
        bool nz12 = false, nz3 = false;
        for (int i = 0; i < 16384; i++) {
            unsigned char v = m[i];
            if (v) {
                int o = i & 3;
                if (o == 1 || o == 2) nz12 = true;
                else if (o == 3) nz3 = true;
            }
        }
        g_mask_mode = nz12 ? 1 : (nz3 ? 2 : 0);
    }
}

__device__ __forceinline__ float mask_neg(const void* maskp, int mm, int idx) {
    if (mm == 0) return ((const int*)maskp)[idx] ? -1e20f : 0.0f;
    if (mm == 1) return ((const unsigned char*)maskp)[idx] ? -1e20f : 0.0f;
    return (((const float*)maskp)[idx] != 0.0f) ? -1e20f : 0.0f;
}

// ---------------- simple copy ----------------
__global__ void copy_kernel(const float* __restrict__ src, float* __restrict__ dst, int n) {
    int i = blockIdx.x * blockDim.x + threadIdx.x;
    if (i < n) dst[i] = src[i];
}

// ---------------- SGEMM: 64x64 tile, BK=16, double-buffered ----------------
// mode 0: single GEMM. mode 1: QKV (z selects B/C of 3).
// mode 2: split-K, z writes its partial to C + z*M*N (no atomics).
__global__ __launch_bounds__(256) void sgemm2(
    const float* __restrict__ A,
    const float* __restrict__ B0, const float* __restrict__ B1, const float* __restrict__ B2,
    float* __restrict__ C0, float* __restrict__ C1, float* __restrict__ C2,
    int M, int N, int K,
    const float* __restrict__ bias, int dorelu, int mode, int nsplit)
{
    __shared__ float As[2][64][17];
    __shared__ float Bs[2][16][64];
    int t = threadIdx.x;
    int tx = t & 15, ty = t >> 4;
    int m0 = blockIdx.y * 64, n0 = blockIdx.x * 64;
    int z = blockIdx.z;

    const float* Bm = B0;
    float* C = C0;
    int Kc = K, k0 = 0;
    if (mode == 1) {
        Bm = (z == 0) ? B0 : (z == 1) ? B1 : B2;
        C  = (z == 0) ? C0 : (z == 1) ? C1 : C2;
    } else if (mode == 2) {
        Kc = K / nsplit;
        k0 = z * Kc;
        C = C0 + (size_t)z * M * N;
    }

    int arow = t >> 2, acol = (t & 3) * 4;
    int brow = t >> 4, bcol = (t & 15) * 4;
    const float* Aptr = A + (m0 + arow) * K + k0 + acol;
    const float* Bptr = Bm + (k0 + brow) * N + n0 + bcol;

    float4 av = *(const float4*)Aptr;
    float4 bv = *(const float4*)Bptr;
    As[0][arow][acol + 0] = av.x; As[0][arow][acol + 1] = av.y;
    As[0][arow][acol + 2] = av.z; As[0][arow][acol + 3] = av.w;
    *(float4*)&Bs[0][brow][bcol] = bv;
    __syncthreads();

    float acc[4][4] = {};
    int nk = Kc / 16;
    int buf = 0;
    for (int kb = 0; kb < nk; kb++) {
        if (kb + 1 < nk) {
            av = *(const float4*)(Aptr + (kb + 1) * 16);
            bv = *(const float4*)(Bptr + (size_t)(kb + 1) * 16 * N);
        }
#pragma unroll
        for (int k2 = 0; k2 < 16; k2++) {
            float a0 = As[buf][ty * 4 + 0][k2];
            float a1 = As[buf][ty * 4 + 1][k2];
            float a2 = As[buf][ty * 4 + 2][k2];
            float a3 = As[buf][ty * 4 + 3][k2];
            float4 b4 = *(float4*)&Bs[buf][k2][tx * 4];
            acc[0][0] += a0 * b4.x; acc[0][1] += a0 * b4.y; acc[0][2] += a0 * b4.z; acc[0][3] += a0 * b4.w;
            acc[1][0] += a1 * b4.x; acc[1][1] += a1 * b4.y; acc[1][2] += a1 * b4.z; acc[1][3] += a1 * b4.w;
            acc[2][0] += a2 * b4.x; acc[2][1] += a2 * b4.y; acc[2][2] += a2 * b4.z; acc[2][3] += a2 * b4.w;
            acc[3][0] += a3 * b4.x; acc[3][1] += a3 * b4.y; acc[3][2] += a3 * b4.z; acc[3][3] += a3 * b4.w;
        }
        if (kb + 1 < nk) {
            int nb = buf ^ 1;
            As[nb][arow][acol + 0] = av.x; As[nb][arow][acol + 1] = av.y;
            As[nb][arow][acol + 2] = av.z; As[nb][arow][acol + 3] = av.w;
            *(float4*)&Bs[nb][brow][bcol] = bv;
            __syncthreads();
            buf = nb;
        }
    }

    int c0 = n0 + tx * 4;
#pragma unroll
    for (int i = 0; i < 4; i++) {
        int r = m0 + ty * 4 + i;
        float4 o;
        o.x = acc[i][0]; o.y = acc[i][1]; o.z = acc[i][2]; o.w = acc[i][3];
        if (dorelu) {
            o.x = fmaxf(o.x + bias[c0 + 0], 0.0f);
            o.y = fmaxf(o.y + bias[c0 + 1], 0.0f);
            o.z = fmaxf(o.z + bias[c0 + 2], 0.0f);
            o.w = fmaxf(o.w + bias[c0 + 3], 0.0f);
        }
        *(float4*)&C[(size_t)r * N + c0] = o;
    }
}

// ---------------- fused flash attention v3: 32-row q tile, reg softmax ----------------
// grid (L/32, NH, B), 256 threads.
// kt/vt XOR swizzle: float4 slot = j*8 + (d4 ^ (j&7)).
#define A3_KT   0                           // 4096 (also Ek / Ev staging)
#define A3_VT   4096                        // 4096
#define A3_QS   8192                        // 32*36 = 1152
#define A3_QR   9344                        // 32*100 = 3200
#define A3_ARL  12544                       // 32*100 = 3200
#define A3_SC   15744                       // 32*132 = 4224
#define A3_OH   19968                       // 3*64*16 = 3072
#define A3_MS   23040                       // 32
#define A3_SS   23072                       // 32
#define A3_FC   23104                       // 32
#define ATTN3_SMEM (23136 * 4)              // 92,544 B

__global__ __launch_bounds__(256) void attn3_kernel(
    const float* __restrict__ q, const float* __restrict__ k,
    const float* __restrict__ v, const float* __restrict__ Ek,
    const int* __restrict__ rel, const void* __restrict__ maskp,
    const float* __restrict__ Ev, float* __restrict__ out)
{
    extern __shared__ float sm[];
    float* kt  = sm + A3_KT;
    float* vt  = sm + A3_VT;
    float* qs  = sm + A3_QS;
    float* qr  = sm + A3_QR;
    float* arl = sm + A3_ARL;
    float* sc  = sm + A3_SC;
    float* oh  = sm + A3_OH;
    float* m_s = sm + A3_MS;
    float* s_s = sm + A3_SS;
    float* fac = sm + A3_FC;
    float4* kt4 = (float4*)kt;
    float4* vt4 = (float4*)vt;

    int t = threadIdx.x;
    int w = t >> 5, l = t & 31;
    int i0 = blockIdx.x * 32, h = blockIdx.y, b = blockIdx.z;
    int mm = g_mask_mode;

    // ---- prolog: q rows, Ek->kt staging, qrel compute, init ----
    for (int idx = t; idx < 32 * 32; idx += 256) {
        int i = idx >> 5, d = idx & 31;
        qs[i * 36 + d] = q[(b * L_ + i0 + i) * H_ + h * 32 + d];
    }
    for (int idx = t; idx < REL_ * 32; idx += 256) kt[idx] = Ek[idx];
    for (int idx = t; idx < 32 * REL_; idx += 256) arl[idx] = 0.0f;
    if (t < 32) { m_s[t] = -3.4e38f; s_s[t] = 0.0f; }
    __syncthreads();

    {   // qr[i][r] = sum_d qs[i][d] * Ek[r][d]
        int i = t >> 3, l8 = t & 7;
        for (int quad = l8; quad < 25; quad += 8) {
            float a0 = 0.f, a1 = 0.f, a2 = 0.f, a3 = 0.f;
#pragma unroll
            for (int d4 = 0; d4 < 8; d4++) {
                float4 qv = *(float4*)&qs[i * 36 + d4 * 4];
                float4 e0 = *(float4*)&kt[(quad * 4 + 0) * 32 + d4 * 4];
                float4 e1 = *(float4*)&kt[(quad * 4 + 1) * 32 + d4 * 4];
                float4 e2 = *(float4*)&kt[(quad * 4 + 2) * 32 + d4 * 4];
                float4 e3 = *(float4*)&kt[(quad * 4 + 3) * 32 + d4 * 4];
                a0 += qv.x * e0.x + qv.y * e0.y + qv.z * e0.z + qv.w * e0.w;
                a1 += qv.x * e1.x + qv.y * e1.y + qv.z * e1.z + qv.w * e1.w;
                a2 += qv.x * e2.x + qv.y * e2.y + qv.z * e2.z + qv.w * e2.w;
                a3 += qv.x * e3.x + qv.y * e3.y + qv.z * e3.z + qv.w * e3.w;
            }
            qr[i * REL_ + quad * 4 + 0] = a0;
            qr[i * REL_ + quad * 4 + 1] = a1;
            qr[i * REL_ + quad * 4 + 2] = a2;
            qr[i * REL_ + quad * 4 + 3] = a3;
        }
    }

    // AV-thread decomposition: t = jq*64 + rp8*8 + d4i
    int jq  = t >> 6;          // j-quarter 0..3
    int rp8 = (t >> 3) & 7;    // row group: rows rp8 + 8k
    int d4i = t & 7;           // dim quad
    float4 o[4];
#pragma unroll
    for (int k4 = 0; k4 < 4; k4++) { o[k4].x = 0.f; o[k4].y = 0.f; o[k4].z = 0.f; o[k4].w = 0.f; }

    int r0 = w * 4;            // scores: warp w owns rows r0..r0+3

    const float4* kg = (const float4*)(k + (size_t)(b * L_) * H_ + h * 32);
    const float4* vg = (const float4*)(v + (size_t)(b * L_) * H_ + h * 32);

    for (int jt = 0; jt < 8; jt++) {
        int j0 = jt * 128;
        __syncthreads();   // protect kt/vt/sc from previous-iter consumers
        for (int idx = t; idx < 1024; idx += 256) {
            int j = idx >> 3, d4 = idx & 7;
            int slot = j * 8 + (d4 ^ (j & 7));
            kt4[slot] = kg[(size_t)(j0 + j) * 64 + d4];
            vt4[slot] = vg[(size_t)(j0 + j) * 64 + d4];
        }
        __syncthreads();

        // ---- scores: 4 rows x 4 cols per thread, fully in registers ----
        float acc[4][4] = {};
#pragma unroll
        for (int d4 = 0; d4 < 8; d4++) {
            float4 qv0 = *(float4*)&qs[(r0 + 0) * 36 + d4 * 4];
            float4 qv1 = *(float4*)&qs[(r0 + 1) * 36 + d4 * 4];
            float4 qv2 = *(float4*)&qs[(r0 + 2) * 36 + d4 * 4];
            float4 qv3 = *(float4*)&qs[(r0 + 3) * 36 + d4 * 4];
#pragma unroll
            for (int c = 0; c < 4; c++) {
                int j = l + 32 * c;
                float4 kv = kt4[j * 8 + (d4 ^ (j & 7))];
                acc[0][c] += qv0.x * kv.x + qv0.y * kv.y + qv0.z * kv.z + qv0.w * kv.w;
                acc[1][c] += qv1.x * kv.x + qv1.y * kv.y + qv1.z * kv.z + qv1.w * kv.w;
                acc[2][c] += qv2.x * kv.x + qv2.y * kv.y + qv2.z * kv.z + qv2.w * kv.w;
                acc[3][c] += qv3.x * kv.x + qv3.y * kv.y + qv3.z * kv.z + qv3.w * kv.w;
            }
        }

        // ---- per-row: finish scores, online softmax, bin — all register-resident ----
#pragma unroll
        for (int rr = 0; rr < 4; rr++) {
            int i = r0 + rr;
            float s[4];
            int rid[4];
#pragma unroll
            for (int c = 0; c < 4; c++) {
                int g = (b * L_ + i0 + i) * L_ + j0 + l + 32 * c;
                rid[c] = rel[g];
                s[c] = (acc[rr][c] + qr[i * REL_ + rid[c]]) * INV_SCALE + mask_neg(maskp, mm, g);
            }
            float mx = fmaxf(fmaxf(s[0], s[1]), fmaxf(s[2], s[3]));
#pragma unroll
            for (int off = 16; off; off >>= 1) mx = fmaxf(mx, __shfl_xor_sync(0xffffffffu, mx, off));
            float m_old = m_s[i];
            float m_new = fmaxf(m_old, mx);
            float f = __expf(m_old - m_new);
            // rescale bins to the new max BEFORE adding this tile's probs
            for (int r = l; r < REL_; r += 32) arl[i * REL_ + r] *= f;
            float ssum = 0.0f;
#pragma unroll
            for (int c = 0; c < 4; c++) {
                float p = __expf(s[c] - m_new);
                sc[i * 132 + l + 32 * c] = p;
                ssum += p;
                if (p != 0.0f) atomicAdd(&arl[i * REL_ + rid[c]], p);
            }
#pragma unroll
            for (int off = 16; off; off >>= 1) ssum += __shfl_xor_sync(0xffffffffu, ssum, off);
            if (l == 0) { m_s[i] = m_new; s_s[i] = s_s[i] * f + ssum; fac[i] = f; }
        }
        __syncthreads();   // fac + all rows' probs visible

        // ---- AV: 4 rows x 4 dims x quarter-j per thread, float4 prob loads ----
        float f0 = fac[rp8 + 0], f1 = fac[rp8 + 8], f2 = fac[rp8 + 16], f3 = fac[rp8 + 24];
        o[0].x *= f0; o[0].y *= f0; o[0].z *= f0; o[0].w *= f0;
        o[1].x *= f1; o[1].y *= f1; o[1].z *= f1; o[1].w *= f1;
        o[2].x *= f2; o[2].y *= f2; o[2].z *= f2; o[2].w *= f2;
        o[3].x *= f3; o[3].y *= f3; o[3].z *= f3; o[3].w *= f3;
        int jlo = jq * 32;
#pragma unroll 2
        for (int gq = 0; gq < 8; gq++) {
            int j = jlo + gq * 4;
            float4 p0 = *(float4*)&sc[(rp8 + 0) * 132 + j];
            float4 p1 = *(float4*)&sc[(rp8 + 8) * 132 + j];
            float4 p2 = *(float4*)&sc[(rp8 + 16) * 132 + j];
            float4 p3 = *(float4*)&sc[(rp8 + 24) * 132 + j];
            float4 v0 = vt4[(j + 0) * 8 + (d4i ^ ((j + 0) & 7))];
            float4 v1 = vt4[(j + 1) * 8 + (d4i ^ ((j + 1) & 7))];
            float4 v2 = vt4[(j + 2) * 8 + (d4i ^ ((j + 2) & 7))];
            float4 v3 = vt4[(j + 3) * 8 + (d4i ^ ((j + 3) & 7))];
            o[0].x += p0.x * v0.x + p0.y * v1.x + p0.z * v2.x + p0.w * v3.x;
            o[0].y += p0.x * v0.y + p0.y * v1.y + p0.z * v2.y + p0.w * v3.y;
            o[0].z += p0.x * v0.z + p0.y * v1.z + p0.z * v2.z + p0.w * v3.z;
            o[0].w += p0.x * v0.w + p0.y * v1.w + p0.z * v2.w + p0.w * v3.w;
            o[1].x += p1.x * v0.x + p1.y * v1.x + p1.z * v2.x + p1.w * v3.x;
            o[1].y += p1.x * v0.y + p1.y * v1.y + p1.z * v2.y + p1.w * v3.y;
            o[1].z += p1.x * v0.z + p1.y * v1.z + p1.z * v2.z + p1.w * v3.z;
            o[1].w += p1.x * v0.w + p1.y * v1.w + p1.z * v2.w + p1.w * v3.w;
            o[2].x += p2.x * v0.x + p2.y * v1.x + p2.z * v2.x + p2.w * v3.x;
            o[2].y += p2.x * v0.y + p2.y * v1.y + p2.z * v2.y + p2.w * v3.y;
            o[2].z += p2.x * v0.z + p2.y * v1.z + p2.z * v2.z + p2.w * v3.z;
            o[2].w += p2.x * v0.w + p2.y * v1.w + p2.z * v2.w + p2.w * v3.w;
            o[3].x += p3.x * v0.x + p3.y * v1.x + p3.z * v2.x + p3.w * v3.x;
            o[3].y += p3.x * v0.y + p3.y * v1.y + p3.z * v2.y + p3.w * v3.y;
            o[3].z += p3.x * v0.z + p3.y * v1.z + p3.z * v2.z + p3.w * v3.z;
            o[3].w += p3.x * v0.w + p3.y * v1.w + p3.z * v2.w + p3.w * v3.w;
        }
    }

    // ---- epilogue ----
    __syncthreads();
    for (int idx = t; idx < REL_ * 32; idx += 256) kt[idx] = Ev[idx];  // stage Ev
    int slot = rp8 * 8 + d4i;
    if (jq > 0) {
        float4* dst = (float4*)&oh[((jq - 1) * 64 + slot) * 16];
#pragma unroll
        for (int k4 = 0; k4 < 4; k4++) dst[k4] = o[k4];
    }
    __syncthreads();
    if (jq == 0) {
#pragma unroll
        for (int qq = 0; qq < 3; qq++) {
            float4* src = (float4*)&oh[(qq * 64 + slot) * 16];
#pragma unroll
            for (int k4 = 0; k4 < 4; k4++) {
                float4 s4 = src[k4];
                o[k4].x += s4.x; o[k4].y += s4.y; o[k4].z += s4.z; o[k4].w += s4.w;
            }
        }
#pragma unroll 4
        for (int r = 0; r < REL_; r++) {
            float4 e = *(float4*)&kt[r * 32 + d4i * 4];
            float w0 = arl[(rp8 + 0) * REL_ + r];
            float w1 = arl[(rp8 + 8) * REL_ + r];
            float w2 = arl[(rp8 + 16) * REL_ + r];
            float w3 = arl[(rp8 + 24) * REL_ + r];
            o[0].x += w0 * e.x; o[0].y += w0 * e.y; o[0].z += w0 * e.z; o[0].w += w0 * e.w;
            o[1].x += w1 * e.x; o[1].y += w1 * e.y; o[1].z += w1 * e.z; o[1].w += w1 * e.w;
            o[2].x += w2 * e.x; o[2].y += w2 * e.y; o[2].z += w2 * e.z; o[2].w += w2 * e.w;
            o[3].x += w3 * e.x; o[3].y += w3 * e.y; o[3].z += w3 * e.z; o[3].w += w3 * e.w;
        }
#pragma unroll
        for (int k4 = 0; k4 < 4; k4++) {
            int r = rp8 + 8 * k4;
            float inv = 1.0f / s_s[r];
            float4 o4;
            o4.x = o[k4].x * inv; o4.y = o[k4].y * inv; o4.z = o[k4].z * inv; o4.w = o[k4].w * inv;
            *(float4*)&out[(size_t)(b * L_ + i0 + r) * H_ + h * 32 + d4i * 4] = o4;
        }
    }
}

// ---------------- bias + residual + LayerNorm; sums nbuf split-K partials ----------------
__global__ __launch_bounds__(256) void ln_kernel(
    const float* __restrict__ tin, const float* __restrict__ bias,
    const float* __restrict__ resid, const float* __restrict__ gam,
    const float* __restrict__ bet, float* __restrict__ out, int nbuf)
{
    int row = blockIdx.x, c = threadIdx.x;
    float vv = bias[c] + resid[row * H_ + c];
    for (int s = 0; s < nbuf; s++) vv += tin[(size_t)s * M_ * H_ + row * H_ + c];
    __shared__ float red[16];
    float s1 = vv, s2 = vv * vv;
#pragma unroll
    for (int off = 16; off; off >>= 1) {
        s1 += __shfl_xor_sync(0xffffffffu, s1, off);
        s2 += __shfl_xor_sync(0xffffffffu, s2, off);
    }
    int w = c >> 5, l = c & 31;
    if (l == 0) { red[w] = s1; red[8 + w] = s2; }
    __syncthreads();
    float t1 = 0.0f, t2 = 0.0f;
#pragma unroll
    for (int ww = 0; ww < 8; ww++) { t1 += red[ww]; t2 += red[8 + ww]; }
    float mean = t1 * (1.0f / 256.0f);
    float var = t2 * (1.0f / 256.0f) - mean * mean;
    out[row * H_ + c] = (vv - mean) * rsqrtf(var + EPS_) * gam[c] + bet[c];
}

// ---------------- launch ----------------
extern "C" void kernel_launch(void* const* d_in, const int* in_sizes, int n_in,
                              void* d_out, int out_size)
{
    (void)in_sizes; (void)n_in; (void)out_size;
    const float* inputs = (const float*)d_in[0];
    const float* Wq = (const float*)d_in[1];
    const float* Wk = (const float*)d_in[2];
    const float* Wv = (const float*)d_in[3];
    const float* Wo = (const float*)d_in[4];
    const float* bo = (const float*)d_in[5];
    const float* W1 = (const float*)d_in[6];
    const float* b1 = (const float*)d_in[7];
    const float* W2 = (const float*)d_in[8];
    const float* b2 = (const float*)d_in[9];
    const float* ln1g = (const float*)d_in[10];
    const float* ln1b = (const float*)d_in[11];
    const float* ln2g = (const float*)d_in[12];
    const float* ln2b = (const float*)d_in[13];
    const float* Ek = (const float*)d_in[14];
    const float* Ev = (const float*)d_in[15];
    const int*   rel = (const int*)d_in[16];
    const void*  mask = d_in[17];

    float *px, *pq, *pk, *pv, *pao, *ptmp, *pffh;
    cudaGetSymbolAddress((void**)&px,  g_x);
    cudaGetSymbolAddress((void**)&pq,  g_q);
    cudaGetSymbolAddress((void**)&pk,  g_k);
    cudaGetSymbolAddress((void**)&pv,  g_v);
    cudaGetSymbolAddress((void**)&pao, g_ao);
    cudaGetSymbolAddress((void**)&ptmp, g_tmp);
    cudaGetSymbolAddress((void**)&pffh, g_ffh);

    cudaFuncSetAttribute(attn3_kernel, cudaFuncAttributeMaxDynamicSharedMemorySize, ATTN3_SMEM);

    detect_mask_kernel<<<1, 1>>>((const unsigned char*)mask);
    copy_kernel<<<(M_ * H_ + 255) / 256, 256>>>(inputs, px, M_ * H_);

    for (int l = 0; l < NL_; l++) {
        const float* wq = Wq + l * H_ * H_;
        const float* wk = Wk + l * H_ * H_;
        const float* wv = Wv + l * H_ * H_;
        const float* wo = Wo + l * H_ * H_;
        const float* w1 = W1 + l * H_ * FF_;
        const float* w2 = W2 + l * FF_ * H_;

        // fused QKV (one launch, 384 CTAs)
        sgemm2<<<dim3(H_ / 64, M_ / 64, 3), 256>>>(
            px, wq, wk, wv, pq, pk, pv, M_, H_, H_, nullptr, 0, 1, 1);

        attn3_kernel<<<dim3(L_ / 32, NH_, B_), 256, ATTN3_SMEM>>>(
            pq, pk, pv, Ek, rel, mask, Ev, pao);

        // Wo: split-K=2, partials to ptmp[0..1]; ln sums them
        sgemm2<<<dim3(H_ / 64, M_ / 64, 2), 256>>>(
            pao, wo, nullptr, nullptr, ptmp, nullptr, nullptr, M_, H_, H_, nullptr, 0, 2, 2);

        ln_kernel<<<M_, 256>>>(ptmp, bo + l * H_, px, ln1g + l * H_, ln1b + l * H_, px, 2);

        // FF1: bias + relu fused
        sgemm2<<<dim3(FF_ / 64, M_ / 64, 1), 256>>>(
            px, w1, nullptr, nullptr, pffh, nullptr, nullptr, M_, FF_, H_, b1 + l * FF_, 1, 0, 1);

        // FF2: split-K=4, partials to ptmp[0..3]; ln sums them
        sgemm2<<<dim3(H_ / 64, M_ / 64, 4), 256>>>(
            pffh, w2, nullptr, nullptr, ptmp, nullptr, nullptr, M_, H_, FF_, nullptr, 0, 2, 4);

        float* dst = (l == NL_ - 1) ? (float*)d_out : px;
        ln_kernel<<<M_, 256>>>(ptmp, b2 + l * H_, px, ln2g + l * H_, ln2b + l * H_, dst, 4);
    }
}

// round 7
// speedup vs baseline: 1.5705x; 1.0226x over previous
#include <cuda_runtime.h>
#include <cuda_bf16.h>
#include <math.h>

// Problem constants
#define B_ 2
#define L_ 1024
#define H_ 256
#define NH_ 8
#define DH_ 32
#define FF_ 1024
#define NL_ 2
#define REL_ 100
#define M_ (B_ * L_)            // 2048 rows
#define INV_SCALE 0.17677669529663687f   // 1/sqrt(32)
#define EPS_ 1e-5f

// ---------------- scratch (device globals; no runtime alloc) ----------------
__device__ float g_x[M_ * H_];
__device__ float g_q[M_ * H_];
__device__ float g_k[M_ * H_];
__device__ float g_v[M_ * H_];
__device__ float g_ao[M_ * H_];
__device__ float g_tmp[4 * M_ * H_];          // up to 4 split-K partial buffers
__device__ float g_ffh[M_ * FF_];
__device__ int   g_mask_mode;                 // 0=int32, 1=uint8, 2=float32

// ---------------- mask dtype detection (deterministic) ----------------
__global__ void detect_mask_kernel(const unsigned char* __restrict__ m) {
    if (threadIdx.x == 0 && blockIdx.x == 0) {
        bool nz12 = false, nz3 = false;
        for (int i = 0; i < 16384; i++) {
            unsigned char v = m[i];
            if (v) {
                int o = i & 3;
                if (o == 1 || o == 2) nz12 = true;
                else if (o == 3) nz3 = true;
            }
        }
        g_mask_mode = nz12 ? 1 : (nz3 ? 2 : 0);
    }
}

__device__ __forceinline__ float mask_neg(const void* maskp, int mm, int idx) {
    if (mm == 0) return ((const int*)maskp)[idx] ? -1e20f : 0.0f;
    if (mm == 1) return ((const unsigned char*)maskp)[idx] ? -1e20f : 0.0f;
    return (((const float*)maskp)[idx] != 0.0f) ? -1e20f : 0.0f;
}

// ---------------- simple copy ----------------
__global__ void copy_kernel(const float* __restrict__ src, float* __restrict__ dst, int n) {
    int i = blockIdx.x * blockDim.x + threadIdx.x;
    if (i < n) dst[i] = src[i];
}

// ---------------- SGEMM: 64x64 tile, BK=16, double-buffered ----------------
// mode 0: single GEMM. mode 1: QKV (z selects B/C of 3).
// mode 2: split-K, z writes its partial to C + z*M*N (no atomics).
__global__ __launch_bounds__(256) void sgemm2(
    const float* __restrict__ A,
    const float* __restrict__ B0, const float* __restrict__ B1, const float* __restrict__ B2,
    float* __restrict__ C0, float* __restrict__ C1, float* __restrict__ C2,
    int M, int N, int K,
    const float* __restrict__ bias, int dorelu, int mode, int nsplit)
{
    __shared__ float As[2][64][17];
    __shared__ float Bs[2][16][64];
    int t = threadIdx.x;
    int tx = t & 15, ty = t >> 4;
    int m0 = blockIdx.y * 64, n0 = blockIdx.x * 64;
    int z = blockIdx.z;

    const float* Bm = B0;
    float* C = C0;
    int Kc = K, k0 = 0;
    if (mode == 1) {
        Bm = (z == 0) ? B0 : (z == 1) ? B1 : B2;
        C  = (z == 0) ? C0 : (z == 1) ? C1 : C2;
    } else if (mode == 2) {
        Kc = K / nsplit;
        k0 = z * Kc;
        C = C0 + (size_t)z * M * N;
    }

    int arow = t >> 2, acol = (t & 3) * 4;
    int brow = t >> 4, bcol = (t & 15) * 4;
    const float* Aptr = A + (m0 + arow) * K + k0 + acol;
    const float* Bptr = Bm + (k0 + brow) * N + n0 + bcol;

    float4 av = *(const float4*)Aptr;
    float4 bv = *(const float4*)Bptr;
    As[0][arow][acol + 0] = av.x; As[0][arow][acol + 1] = av.y;
    As[0][arow][acol + 2] = av.z; As[0][arow][acol + 3] = av.w;
    *(float4*)&Bs[0][brow][bcol] = bv;
    __syncthreads();

    float acc[4][4] = {};
    int nk = Kc / 16;
    int buf = 0;
    for (int kb = 0; kb < nk; kb++) {
        if (kb + 1 < nk) {
            av = *(const float4*)(Aptr + (kb + 1) * 16);
            bv = *(const float4*)(Bptr + (size_t)(kb + 1) * 16 * N);
        }
#pragma unroll
        for (int k2 = 0; k2 < 16; k2++) {
            float a0 = As[buf][ty * 4 + 0][k2];
            float a1 = As[buf][ty * 4 + 1][k2];
            float a2 = As[buf][ty * 4 + 2][k2];
            float a3 = As[buf][ty * 4 + 3][k2];
            float4 b4 = *(float4*)&Bs[buf][k2][tx * 4];
            acc[0][0] += a0 * b4.x; acc[0][1] += a0 * b4.y; acc[0][2] += a0 * b4.z; acc[0][3] += a0 * b4.w;
            acc[1][0] += a1 * b4.x; acc[1][1] += a1 * b4.y; acc[1][2] += a1 * b4.z; acc[1][3] += a1 * b4.w;
            acc[2][0] += a2 * b4.x; acc[2][1] += a2 * b4.y; acc[2][2] += a2 * b4.z; acc[2][3] += a2 * b4.w;
            acc[3][0] += a3 * b4.x; acc[3][1] += a3 * b4.y; acc[3][2] += a3 * b4.z; acc[3][3] += a3 * b4.w;
        }
        if (kb + 1 < nk) {
            int nb = buf ^ 1;
            As[nb][arow][acol + 0] = av.x; As[nb][arow][acol + 1] = av.y;
            As[nb][arow][acol + 2] = av.z; As[nb][arow][acol + 3] = av.w;
            *(float4*)&Bs[nb][brow][bcol] = bv;
            __syncthreads();
            buf = nb;
        }
    }

    int c0 = n0 + tx * 4;
#pragma unroll
    for (int i = 0; i < 4; i++) {
        int r = m0 + ty * 4 + i;
        float4 o;
        o.x = acc[i][0]; o.y = acc[i][1]; o.z = acc[i][2]; o.w = acc[i][3];
        if (dorelu) {
            o.x = fmaxf(o.x + bias[c0 + 0], 0.0f);
            o.y = fmaxf(o.y + bias[c0 + 1], 0.0f);
            o.z = fmaxf(o.z + bias[c0 + 2], 0.0f);
            o.w = fmaxf(o.w + bias[c0 + 3], 0.0f);
        }
        *(float4*)&C[(size_t)r * N + c0] = o;
    }
}

// ---------------- fused flash attention v4: prefetch + hoisted rel/mask ----------------
// grid (L/32, NH, B), 256 threads, 2 CTAs/SM.
// kt/vt XOR swizzle: float4 slot = j*8 + (d4 ^ (j&7)).
#define A4_KT   0                           // 4096 (also Ek / Ev staging)
#define A4_VT   4096                        // 4096
#define A4_QS   8192                        // 32*32 = 1024 (warp-broadcast loads)
#define A4_QR   9216                        // 32*100 = 3200
#define A4_ARL  12416                       // 32*100 = 3200
#define A4_SC   15616                       // 32*128 = 4096 (aliased as oh in epilogue)
#define A4_MS   19712                       // 32
#define A4_SS   19744                       // 32
#define A4_FC   19776                       // 32
#define ATTN4_SMEM (19808 * 4)              // 79,232 B

__global__ __launch_bounds__(256, 2) void attn4_kernel(
    const float* __restrict__ q, const float* __restrict__ k,
    const float* __restrict__ v, const float* __restrict__ Ek,
    const int* __restrict__ rel, const void* __restrict__ maskp,
    const float* __restrict__ Ev, float* __restrict__ out)
{
    extern __shared__ float sm[];
    float* kt  = sm + A4_KT;
    float* vt  = sm + A4_VT;
    float* qs  = sm + A4_QS;
    float* qr  = sm + A4_QR;
    float* arl = sm + A4_ARL;
    float* sc  = sm + A4_SC;
    float* m_s = sm + A4_MS;
    float* s_s = sm + A4_SS;
    float* fac = sm + A4_FC;
    float4* kt4 = (float4*)kt;
    float4* vt4 = (float4*)vt;

    int t = threadIdx.x;
    int w = t >> 5, l = t & 31;
    int i0 = blockIdx.x * 32, h = blockIdx.y, b = blockIdx.z;
    int mm = g_mask_mode;

    // ---- prolog: q rows, Ek->kt staging, qrel compute, init ----
    for (int idx = t; idx < 32 * 32; idx += 256) {
        int i = idx >> 5, d = idx & 31;
        qs[i * 32 + d] = q[(b * L_ + i0 + i) * H_ + h * 32 + d];
    }
    for (int idx = t; idx < REL_ * 32; idx += 256) kt[idx] = Ek[idx];
    for (int idx = t; idx < 32 * REL_; idx += 256) arl[idx] = 0.0f;
    if (t < 32) { m_s[t] = -3.4e38f; s_s[t] = 0.0f; }
    __syncthreads();

    {   // qr[i][r] = sum_d qs[i][d] * Ek[r][d]
        int i = t >> 3, l8 = t & 7;
        for (int quad = l8; quad < 25; quad += 8) {
            float a0 = 0.f, a1 = 0.f, a2 = 0.f, a3 = 0.f;
#pragma unroll
            for (int d4 = 0; d4 < 8; d4++) {
                float4 qv = *(float4*)&qs[i * 32 + d4 * 4];
                float4 e0 = *(float4*)&kt[(quad * 4 + 0) * 32 + d4 * 4];
                float4 e1 = *(float4*)&kt[(quad * 4 + 1) * 32 + d4 * 4];
                float4 e2 = *(float4*)&kt[(quad * 4 + 2) * 32 + d4 * 4];
                float4 e3 = *(float4*)&kt[(quad * 4 + 3) * 32 + d4 * 4];
                a0 += qv.x * e0.x + qv.y * e0.y + qv.z * e0.z + qv.w * e0.w;
                a1 += qv.x * e1.x + qv.y * e1.y + qv.z * e1.z + qv.w * e1.w;
                a2 += qv.x * e2.x + qv.y * e2.y + qv.z * e2.z + qv.w * e2.w;
                a3 += qv.x * e3.x + qv.y * e3.y + qv.z * e3.z + qv.w * e3.w;
            }
            qr[i * REL_ + quad * 4 + 0] = a0;
            qr[i * REL_ + quad * 4 + 1] = a1;
            qr[i * REL_ + quad * 4 + 2] = a2;
            qr[i * REL_ + quad * 4 + 3] = a3;
        }
    }

    // AV-thread decomposition: t = jq*64 + rp8*8 + d4i
    int jq  = t >> 6;          // j-quarter 0..3
    int rp8 = (t >> 3) & 7;    // row group: rows rp8 + 8k
    int d4i = t & 7;           // dim quad
    float4 o[4];
#pragma unroll
    for (int k4 = 0; k4 < 4; k4++) { o[k4].x = 0.f; o[k4].y = 0.f; o[k4].z = 0.f; o[k4].w = 0.f; }

    int r0 = w * 4;            // scores: warp w owns rows r0..r0+3

    const float4* kg = (const float4*)(k + (size_t)(b * L_) * H_ + h * 32);
    const float4* vg = (const float4*)(v + (size_t)(b * L_) * H_ + h * 32);

    // register prefetch of tile 0
    float4 pk[4], pv[4];
#pragma unroll
    for (int it = 0; it < 4; it++) {
        int idx = t + it * 256;
        int j = idx >> 3, d4 = idx & 7;
        pk[it] = kg[(size_t)j * 64 + d4];
        pv[it] = vg[(size_t)j * 64 + d4];
    }

    for (int jt = 0; jt < 8; jt++) {
        int j0 = jt * 128;
        __syncthreads();   // previous tile's consumers done with kt/vt/sc
        // ---- store prefetched tile to smem (swizzled) ----
#pragma unroll
        for (int it = 0; it < 4; it++) {
            int idx = t + it * 256;
            int j = idx >> 3, d4 = idx & 7;
            int slot = j * 8 + (d4 ^ (j & 7));
            kt4[slot] = pk[it];
            vt4[slot] = pv[it];
        }
        __syncthreads();
        // ---- issue prefetch for next tile (latency hidden behind compute) ----
        if (jt < 7) {
            int j0n = j0 + 128;
#pragma unroll
            for (int it = 0; it < 4; it++) {
                int idx = t + it * 256;
                int j = idx >> 3, d4 = idx & 7;
                pk[it] = kg[(size_t)(j0n + j) * 64 + d4];
                pv[it] = vg[(size_t)(j0n + j) * 64 + d4];
            }
        }

        // ---- hoisted rel/mask loads (overlap QK compute) ----
        unsigned rid_p[4];
        unsigned mbits = 0;
#pragma unroll
        for (int rr = 0; rr < 4; rr++) {
            int base = (b * L_ + i0 + r0 + rr) * L_ + j0 + l;
            unsigned pkk = 0;
#pragma unroll
            for (int c = 0; c < 4; c++) {
                int g = base + 32 * c;
                pkk |= ((unsigned)rel[g]) << (8 * c);
                if (mask_neg(maskp, mm, g) != 0.0f) mbits |= 1u << (rr * 4 + c);
            }
            rid_p[rr] = pkk;
        }

        // ---- scores: 4 rows x 4 cols per thread ----
        float acc[4][4] = {};
#pragma unroll
        for (int d4 = 0; d4 < 8; d4++) {
            float4 qv0 = *(float4*)&qs[(r0 + 0) * 32 + d4 * 4];
            float4 qv1 = *(float4*)&qs[(r0 + 1) * 32 + d4 * 4];
            float4 qv2 = *(float4*)&qs[(r0 + 2) * 32 + d4 * 4];
            float4 qv3 = *(float4*)&qs[(r0 + 3) * 32 + d4 * 4];
#pragma unroll
            for (int c = 0; c < 4; c++) {
                int j = l + 32 * c;
                float4 kv = kt4[j * 8 + (d4 ^ (j & 7))];
                acc[0][c] += qv0.x * kv.x + qv0.y * kv.y + qv0.z * kv.z + qv0.w * kv.w;
                acc[1][c] += qv1.x * kv.x + qv1.y * kv.y + qv1.z * kv.z + qv1.w * kv.w;
                acc[2][c] += qv2.x * kv.x + qv2.y * kv.y + qv2.z * kv.z + qv2.w * kv.w;
                acc[3][c] += qv3.x * kv.x + qv3.y * kv.y + qv3.z * kv.z + qv3.w * kv.w;
            }
        }

        // ---- per-row: finish scores, online softmax, bin ----
#pragma unroll
        for (int rr = 0; rr < 4; rr++) {
            int i = r0 + rr;
            float s[4];
            int rid[4];
#pragma unroll
            for (int c = 0; c < 4; c++) {
                rid[c] = (rid_p[rr] >> (8 * c)) & 0xFF;
                float nm = ((mbits >> (rr * 4 + c)) & 1u) ? -1e20f : 0.0f;
                s[c] = (acc[rr][c] + qr[i * REL_ + rid[c]]) * INV_SCALE + nm;
            }
            float mx = fmaxf(fmaxf(s[0], s[1]), fmaxf(s[2], s[3]));
#pragma unroll
            for (int off = 16; off; off >>= 1) mx = fmaxf(mx, __shfl_xor_sync(0xffffffffu, mx, off));
            float m_old = m_s[i];
            float m_new = fmaxf(m_old, mx);
            float f = __expf(m_old - m_new);
            if (f != 1.0f) {   // rescale bins only when the max moved (warp-uniform)
                for (int r = l; r < REL_; r += 32) arl[i * REL_ + r] *= f;
            }
            float ssum = 0.0f;
#pragma unroll
            for (int c = 0; c < 4; c++) {
                float p = __expf(s[c] - m_new);
                sc[i * 128 + l + 32 * c] = p;
                ssum += p;
                if (p != 0.0f) atomicAdd(&arl[i * REL_ + rid[c]], p);
            }
#pragma unroll
            for (int off = 16; off; off >>= 1) ssum += __shfl_xor_sync(0xffffffffu, ssum, off);
            if (l == 0) { m_s[i] = m_new; s_s[i] = s_s[i] * f + ssum; fac[i] = f; }
        }
        __syncthreads();   // fac + all rows' probs visible

        // ---- AV: 4 rows x 4 dims x quarter-j per thread, float4 prob loads ----
        float f0 = fac[rp8 + 0], f1 = fac[rp8 + 8], f2 = fac[rp8 + 16], f3 = fac[rp8 + 24];
        o[0].x *= f0; o[0].y *= f0; o[0].z *= f0; o[0].w *= f0;
        o[1].x *= f1; o[1].y *= f1; o[1].z *= f1; o[1].w *= f1;
        o[2].x *= f2; o[2].y *= f2; o[2].z *= f2; o[2].w *= f2;
        o[3].x *= f3; o[3].y *= f3; o[3].z *= f3; o[3].w *= f3;
        int jlo = jq * 32;
#pragma unroll 2
        for (int gq = 0; gq < 8; gq++) {
            int j = jlo + gq * 4;
            float4 p0 = *(float4*)&sc[(rp8 + 0) * 128 + j];
            float4 p1 = *(float4*)&sc[(rp8 + 8) * 128 + j];
            float4 p2 = *(float4*)&sc[(rp8 + 16) * 128 + j];
            float4 p3 = *(float4*)&sc[(rp8 + 24) * 128 + j];
            float4 v0 = vt4[(j + 0) * 8 + (d4i ^ ((j + 0) & 7))];
            float4 v1 = vt4[(j + 1) * 8 + (d4i ^ ((j + 1) & 7))];
            float4 v2 = vt4[(j + 2) * 8 + (d4i ^ ((j + 2) & 7))];
            float4 v3 = vt4[(j + 3) * 8 + (d4i ^ ((j + 3) & 7))];
            o[0].x += p0.x * v0.x + p0.y * v1.x + p0.z * v2.x + p0.w * v3.x;
            o[0].y += p0.x * v0.y + p0.y * v1.y + p0.z * v2.y + p0.w * v3.y;
            o[0].z += p0.x * v0.z + p0.y * v1.z + p0.z * v2.z + p0.w * v3.z;
            o[0].w += p0.x * v0.w + p0.y * v1.w + p0.z * v2.w + p0.w * v3.w;
            o[1].x += p1.x * v0.x + p1.y * v1.x + p1.z * v2.x + p1.w * v3.x;
            o[1].y += p1.x * v0.y + p1.y * v1.y + p1.z * v2.y + p1.w * v3.y;
            o[1].z += p1.x * v0.z + p1.y * v1.z + p1.z * v2.z + p1.w * v3.z;
            o[1].w += p1.x * v0.w + p1.y * v1.w + p1.z * v2.w + p1.w * v3.w;
            o[2].x += p2.x * v0.x + p2.y * v1.x + p2.z * v2.x + p2.w * v3.x;
            o[2].y += p2.x * v0.y + p2.y * v1.y + p2.z * v2.y + p2.w * v3.y;
            o[2].z += p2.x * v0.z + p2.y * v1.z + p2.z * v2.z + p2.w * v3.z;
            o[2].w += p2.x * v0.w + p2.y * v1.w + p2.z * v2.w + p2.w * v3.w;
            o[3].x += p3.x * v0.x + p3.y * v1.x + p3.z * v2.x + p3.w * v3.x;
            o[3].y += p3.x * v0.y + p3.y * v1.y + p3.z * v2.y + p3.w * v3.y;
            o[3].z += p3.x * v0.z + p3.y * v1.z + p3.z * v2.z + p3.w * v3.z;
            o[3].w += p3.x * v0.w + p3.y * v1.w + p3.z * v2.w + p3.w * v3.w;
        }
    }

    // ---- epilogue (oh aliases sc; Ev staged in kt) ----
    __syncthreads();
    float* oh = sc;
    for (int idx = t; idx < REL_ * 32; idx += 256) kt[idx] = Ev[idx];
    int slot = rp8 * 8 + d4i;
    if (jq > 0) {
        float4* dst = (float4*)&oh[((jq - 1) * 64 + slot) * 16];
#pragma unroll
        for (int k4 = 0; k4 < 4; k4++) dst[k4] = o[k4];
    }
    __syncthreads();
    if (jq == 0) {
#pragma unroll
        for (int qq = 0; qq < 3; qq++) {
            float4* src = (float4*)&oh[(qq * 64 + slot) * 16];
#pragma unroll
            for (int k4 = 0; k4 < 4; k4++) {
                float4 s4 = src[k4];
                o[k4].x += s4.x; o[k4].y += s4.y; o[k4].z += s4.z; o[k4].w += s4.w;
            }
        }
#pragma unroll 4
        for (int r = 0; r < REL_; r++) {
            float4 e = *(float4*)&kt[r * 32 + d4i * 4];
            float w0 = arl[(rp8 + 0) * REL_ + r];
            float w1 = arl[(rp8 + 8) * REL_ + r];
            float w2 = arl[(rp8 + 16) * REL_ + r];
            float w3 = arl[(rp8 + 24) * REL_ + r];
            o[0].x += w0 * e.x; o[0].y += w0 * e.y; o[0].z += w0 * e.z; o[0].w += w0 * e.w;
            o[1].x += w1 * e.x; o[1].y += w1 * e.y; o[1].z += w1 * e.z; o[1].w += w1 * e.w;
            o[2].x += w2 * e.x; o[2].y += w2 * e.y; o[2].z += w2 * e.z; o[2].w += w2 * e.w;
            o[3].x += w3 * e.x; o[3].y += w3 * e.y; o[3].z += w3 * e.z; o[3].w += w3 * e.w;
        }
#pragma unroll
        for (int k4 = 0; k4 < 4; k4++) {
            int r = rp8 + 8 * k4;
            float inv = 1.0f / s_s[r];
            float4 o4;
            o4.x = o[k4].x * inv; o4.y = o[k4].y * inv; o4.z = o[k4].z * inv; o4.w = o[k4].w * inv;
            *(float4*)&out[(size_t)(b * L_ + i0 + r) * H_ + h * 32 + d4i * 4] = o4;
        }
    }
}

// ---------------- bias + residual + LayerNorm; sums nbuf split-K partials ----------------
__global__ __launch_bounds__(256) void ln_kernel(
    const float* __restrict__ tin, const float* __restrict__ bias,
    const float* __restrict__ resid, const float* __restrict__ gam,
    const float* __restrict__ bet, float* __restrict__ out, int nbuf)
{
    int row = blockIdx.x, c = threadIdx.x;
    float vv = bias[c] + resid[row * H_ + c];
    for (int s = 0; s < nbuf; s++) vv += tin[(size_t)s * M_ * H_ + row * H_ + c];
    __shared__ float red[16];
    float s1 = vv, s2 = vv * vv;
#pragma unroll
    for (int off = 16; off; off >>= 1) {
        s1 += __shfl_xor_sync(0xffffffffu, s1, off);
        s2 += __shfl_xor_sync(0xffffffffu, s2, off);
    }
    int w = c >> 5, l = c & 31;
    if (l == 0) { red[w] = s1; red[8 + w] = s2; }
    __syncthreads();
    float t1 = 0.0f, t2 = 0.0f;
#pragma unroll
    for (int ww = 0; ww < 8; ww++) { t1 += red[ww]; t2 += red[8 + ww]; }
    float mean = t1 * (1.0f / 256.0f);
    float var = t2 * (1.0f / 256.0f) - mean * mean;
    out[row * H_ + c] = (vv - mean) * rsqrtf(var + EPS_) * gam[c] + bet[c];
}

// ---------------- launch ----------------
extern "C" void kernel_launch(void* const* d_in, const int* in_sizes, int n_in,
                              void* d_out, int out_size)
{
    (void)in_sizes; (void)n_in; (void)out_size;
    const float* inputs = (const float*)d_in[0];
    const float* Wq = (const float*)d_in[1];
    const float* Wk = (const float*)d_in[2];
    const float* Wv = (const float*)d_in[3];
    const float* Wo = (const float*)d_in[4];
    const float* bo = (const float*)d_in[5];
    const float* W1 = (const float*)d_in[6];
    const float* b1 = (const float*)d_in[7];
    const float* W2 = (const float*)d_in[8];
    const float* b2 = (const float*)d_in[9];
    const float* ln1g = (const float*)d_in[10];
    const float* ln1b = (const float*)d_in[11];
    const float* ln2g = (const float*)d_in[12];
    const float* ln2b = (const float*)d_in[13];
    const float* Ek = (const float*)d_in[14];
    const float* Ev = (const float*)d_in[15];
    const int*   rel = (const int*)d_in[16];
    const void*  mask = d_in[17];

    float *px, *pq, *pk, *pv, *pao, *ptmp, *pffh;
    cudaGetSymbolAddress((void**)&px,  g_x);
    cudaGetSymbolAddress((void**)&pq,  g_q);
    cudaGetSymbolAddress((void**)&pk,  g_k);
    cudaGetSymbolAddress((void**)&pv,  g_v);
    cudaGetSymbolAddress((void**)&pao, g_ao);
    cudaGetSymbolAddress((void**)&ptmp, g_tmp);
    cudaGetSymbolAddress((void**)&pffh, g_ffh);

    cudaFuncSetAttribute(attn4_kernel, cudaFuncAttributeMaxDynamicSharedMemorySize, ATTN4_SMEM);

    detect_mask_kernel<<<1, 1>>>((const unsigned char*)mask);
    copy_kernel<<<(M_ * H_ + 255) / 256, 256>>>(inputs, px, M_ * H_);

    for (int l = 0; l < NL_; l++) {
        const float* wq = Wq + l * H_ * H_;
        const float* wk = Wk + l * H_ * H_;
        const float* wv = Wv + l * H_ * H_;
        const float* wo = Wo + l * H_ * H_;
        const float* w1 = W1 + l * H_ * FF_;
        const float* w2 = W2 + l * FF_ * H_;

        // fused QKV (one launch, 384 CTAs)
        sgemm2<<<dim3(H_ / 64, M_ / 64, 3), 256>>>(
            px, wq, wk, wv, pq, pk, pv, M_, H_, H_, nullptr, 0, 1, 1);

        attn4_kernel<<<dim3(L_ / 32, NH_, B_), 256, ATTN4_SMEM>>>(
            pq, pk, pv, Ek, rel, mask, Ev, pao);

        // Wo: split-K=2, partials to ptmp[0..1]; ln sums them
        sgemm2<<<dim3(H_ / 64, M_ / 64, 2), 256>>>(
            pao, wo, nullptr, nullptr, ptmp, nullptr, nullptr, M_, H_, H_, nullptr, 0, 2, 2);

        ln_kernel<<<M_, 256>>>(ptmp, bo + l * H_, px, ln1g + l * H_, ln1b + l * H_, px, 2);

        // FF1: bias + relu fused
        sgemm2<<<dim3(FF_ / 64, M_ / 64, 1), 256>>>(
            px, w1, nullptr, nullptr, pffh, nullptr, nullptr, M_, FF_, H_, b1 + l * FF_, 1, 0, 1);

        // FF2: split-K=4, partials to ptmp[0..3]; ln sums them
        sgemm2<<<dim3(H_ / 64, M_ / 64, 4), 256>>>(
            pffh, w2, nullptr, nullptr, ptmp, nullptr, nullptr, M_, H_, FF_, nullptr, 0, 2, 4);

        float* dst = (l == NL_ - 1) ? (float*)d_out : px;
        ln_kernel<<<M_, 256>>>(ptmp, b2 + l * H_, px, ln2g + l * H_, ln2b + l * H_, dst, 4);
    }
}